// round 10
// baseline (speedup 1.0000x reference)
#include <cuda_runtime.h>
#include <cuda_bf16.h>
#include <cuda_fp16.h>
#include <math.h>
#include <stdint.h>

#define N_NODES 100000
#define NPAD    100096
#define N_EDGES 3200000
#define NP1     100001
#define NSCAN_BLOCKS 98

#define LDAB 264                       // A smem row stride (bf16): [hi 128 | lo 128 | pad]
#define A_BYTES (128 * LDAB * 2)       // 67584
#define WT_TILE_BYTES 65536            // packed B tile: 16 nb x 8 ks x 512B
#define BRING_OFF A_BYTES              // B ring: 8 warps x 2 stages x 2048B
#define MM_SMEM (A_BYTES + 8 * 2 * 2048)   // 100352

// ======================= device scratch =======================
__device__ int    g_rowptr[NP1];
__device__ int    g_bsum[128];
__device__ int    g_pos[N_NODES];
__device__ int    g_ecol[N_EDGES];
__device__ float  g_eval[N_EDGES];
__device__ float  g_h0[(size_t)NPAD * 128];   // split act buffer A (512B/row: hi|lo)
__device__ float  g_h1[(size_t)NPAD * 128];   // split act buffer B
__device__ __half g_supn[(size_t)NPAD * 128];
__device__ float  g_self[(size_t)NPAD * 128];
__device__ __nv_bfloat16 g_wt[9 * 32768];

// ======================= helpers =======================
__device__ __forceinline__ uint32_t smem_u32(const void* p) {
    uint32_t a;
    asm("{ .reg .u64 t; cvta.to.shared.u64 t, %1; cvt.u32.u64 %0, t; }" : "=r"(a) : "l"(p));
    return a;
}
__device__ __forceinline__ void ldsm_x4(unsigned* r, uint32_t addr) {
    asm volatile("ldmatrix.sync.aligned.m8n8.x4.shared.b16 {%0,%1,%2,%3}, [%4];"
        : "=r"(r[0]), "=r"(r[1]), "=r"(r[2]), "=r"(r[3]) : "r"(addr));
}
__device__ __forceinline__ void mma_bf16(float* c, const unsigned* a, unsigned b0, unsigned b1) {
    asm volatile("mma.sync.aligned.m16n8k16.row.col.f32.bf16.bf16.f32 "
        "{%0,%1,%2,%3}, {%4,%5,%6,%7}, {%8,%9}, {%0,%1,%2,%3};"
        : "+f"(c[0]), "+f"(c[1]), "+f"(c[2]), "+f"(c[3])
        : "r"(a[0]), "r"(a[1]), "r"(a[2]), "r"(a[3]), "r"(b0), "r"(b1));
}
__device__ __forceinline__ void cpasync16(uint32_t dst, const void* src) {
    asm volatile("cp.async.cg.shared.global [%0], [%1], 16;" :: "r"(dst), "l"(src));
}
__device__ __forceinline__ unsigned pk(float a, float b) {
    __nv_bfloat162 h = __floats2bfloat162_rn(a, b);
    return *(unsigned*)&h;
}
__device__ __forceinline__ void split2(float a0, float a1, unsigned& hi, unsigned& lo) {
    __nv_bfloat16 h0 = __float2bfloat16_rn(a0);
    __nv_bfloat16 h1 = __float2bfloat16_rn(a1);
    hi = pk(__bfloat162float(h0), __bfloat162float(h1));
    lo = pk(a0 - __bfloat162float(h0), a1 - __bfloat162float(h1));
}
__device__ __forceinline__ void split_store_rm(char* buf, int R, int lane, const float* v) {
    unsigned h01, h23, l01, l23;
    split2(v[0], v[1], h01, l01);
    split2(v[2], v[3], h23, l23);
    char* p = buf + (size_t)R * 512 + lane * 8;
    *(uint2*)p = make_uint2(h01, h23);
    *(uint2*)(p + 256) = make_uint2(l01, l23);
}
__device__ __forceinline__ void split_load_rm(const char* buf, int R, int lane, float* v) {
    const char* p = buf + (size_t)R * 512 + lane * 8;
    uint2 h = *(const uint2*)p;
    uint2 l = *(const uint2*)(p + 256);
    float2 fh0 = __bfloat1622float2(*(__nv_bfloat162*)&h.x);
    float2 fh1 = __bfloat1622float2(*(__nv_bfloat162*)&h.y);
    float2 fl0 = __bfloat1622float2(*(__nv_bfloat162*)&l.x);
    float2 fl1 = __bfloat1622float2(*(__nv_bfloat162*)&l.y);
    v[0] = fh0.x + fl0.x; v[1] = fh0.y + fl0.y;
    v[2] = fh1.x + fl1.x; v[3] = fh1.y + fl1.y;
}

// ======================= CSR build =======================
__global__ void k_zero_rowptr() {
    int i = blockIdx.x * blockDim.x + threadIdx.x;
    if (i < NP1) g_rowptr[i] = 0;
}
__global__ void k_hist(const int* __restrict__ rows) {
    int e = blockIdx.x * blockDim.x + threadIdx.x;
    if (e < N_EDGES) atomicAdd(&g_rowptr[rows[e] + 1], 1);
}
__global__ void k_scan1() {
    __shared__ int s[1024];
    int t = threadIdx.x, i = blockIdx.x * 1024 + t;
    int v = (i < NP1) ? g_rowptr[i] : 0;
    s[t] = v; __syncthreads();
    #pragma unroll
    for (int off = 1; off < 1024; off <<= 1) {
        int tv = 0;
        if (t >= off) tv = s[t - off];
        __syncthreads(); s[t] += tv; __syncthreads();
    }
    if (i < NP1) g_rowptr[i] = s[t];
    if (t == 1023) g_bsum[blockIdx.x] = s[1023];
}
__global__ void k_scan2() {
    int acc = 0;
    for (int b = 0; b < NSCAN_BLOCKS; b++) { acc += g_bsum[b]; g_bsum[b] = acc; }
}
__global__ void k_scan3() {
    int b = blockIdx.x;
    int i = b * 1024 + threadIdx.x;
    int add = b ? g_bsum[b - 1] : 0;
    if (i < NP1) {
        int v = g_rowptr[i] + add;
        g_rowptr[i] = v;
        if (i < N_NODES) g_pos[i] = v;
    }
}
__global__ void k_fill(const int* __restrict__ rows, const int* __restrict__ cols,
                       const float* __restrict__ vals) {
    int e = blockIdx.x * blockDim.x + threadIdx.x;
    if (e >= N_EDGES) return;
    int r = rows[e];
    int p = atomicAdd(&g_pos[r], 1);
    g_ecol[p] = cols[e];
    g_eval[p] = vals[e];
}

// ======================= weight prep: pack B in mma-fragment order ==============
__global__ void k_wprep(const float* __restrict__ fc1w, const float* __restrict__ fc2w,
                        const float* __restrict__ w0n, const float* __restrict__ w0s,
                        const float* __restrict__ w1n, const float* __restrict__ w1s,
                        const float* __restrict__ w2n, const float* __restrict__ w2s,
                        const float* __restrict__ w3n, const float* __restrict__ w3s,
                        __nv_bfloat16* __restrict__ wt)
{
    int t = blockIdx.y, n = blockIdx.x, k = threadIdx.x;
    float v;
    switch (t) {
        case 0: v = fc1w[n * 128 + k]; break;
        case 1: v = fc2w[n * 128 + k]; break;
        case 2: v = w0n[k * 128 + n]; break;
        case 3: v = w0s[k * 128 + n]; break;
        case 4: v = w1n[k * 128 + n]; break;
        case 5: v = w1s[k * 128 + n]; break;
        case 6: v = w2n[k * 128 + n]; break;
        case 7: v = w2s[k * 128 + n]; break;
        default: v = (n < 64) ? w3n[k * 64 + n] : w3s[k * 64 + (n - 64)]; break;
    }
    __nv_bfloat16 hi = __float2bfloat16_rn(v);
    __nv_bfloat16 lo = __float2bfloat16_rn(v - __bfloat162float(hi));

    int ks = k >> 4, kk = k & 15;
    int q, e;
    if (kk < 8) { q = kk >> 1; e = kk & 1; }
    else        { q = (kk - 8) >> 1; e = 2 + (kk & 1); }
    int nb = n >> 3, n7 = n & 7;
    char* base = (char*)wt + (size_t)t * WT_TILE_BYTES
               + ((nb * 8 + ks) * 512) + n7 * 64 + q * 16;
    *(__nv_bfloat16*)(base + e * 2)     = hi;
    *(__nv_bfloat16*)(base + 8 + e * 2) = lo;
}

// ======================= X prep: f32 -> split rows =======================
__global__ __launch_bounds__(256) void k_xprep(const float* __restrict__ X, char* __restrict__ dst) {
    int R = blockIdx.x * 8 + (threadIdx.x >> 5);
    int lane = threadIdx.x & 31;
    float v[4] = {0.f, 0.f, 0.f, 0.f};
    if (R < N_NODES) {
        float4 f = *(const float4*)&X[(size_t)R * 128 + lane * 4];
        v[0] = f.x; v[1] = f.y; v[2] = f.z; v[3] = f.w;
    }
    split_store_rm(dst, R, lane, v);
}

// ======================= bf16 GEMM: cp.async A + warp-private B ring ============
// modes: 0 = bias+relu -> split rows o0 ; 1 = fp16 supn (ld128) ;
//        2 = f32 self (ld128) ; 3 = split64: wn<2 -> fp16 o0 (ld64), wn>=2 -> f32 o1 (ld64)
__global__ __launch_bounds__(256, 2) void k_mm(
    const char* __restrict__ Asp,
    const __nv_bfloat16* __restrict__ Bw,
    const float* __restrict__ bias,
    void* __restrict__ o0, int m0,
    void* __restrict__ o1, int m1,
    int nH)
{
    extern __shared__ __nv_bfloat16 As[];   // A: 128 x LDAB ; then B ring

    const int tid = threadIdx.x, wid = tid >> 5, lane = tid & 31;
    const int wm = wid >> 2, wn = wid & 3;   // warp tile: 64 rows x 32 cols
    const int row0 = blockIdx.x * 128;
    const uint32_t sbase = smem_u32(As);
    const uint32_t bring = sbase + BRING_OFF + wid * 4096 + lane * 16;   // +stage*2048 +j*512
    char* brd = (char*)As + BRING_OFF + wid * 4096 + lane * 16;
    const int steps = nH * 8;

    // global B source for (step s, j): lane copies its own 16B fragment
    const char* bsrc0 = (const char*)Bw + (size_t)lane * 16 + (size_t)(wn * 4) * 8 * 512;
    // block offset for (nh, ks, j): nh*WT + j*8*512 + ks*512

    // ---- prologue: cp.async A tile + B step 0 ----
    {
        const char* gsrc = Asp + (size_t)row0 * 512;
        #pragma unroll
        for (int it = 0; it < 16; it++) {
            int i = tid + 256 * it;          // 4096 x 16B
            int r = i >> 5, c = i & 31;
            cpasync16(sbase + r * (LDAB * 2) + c * 16, gsrc + (size_t)i * 16);
        }
        asm volatile("cp.async.commit_group;" ::: "memory");
        #pragma unroll
        for (int j = 0; j < 4; j++)
            cpasync16(bring + j * 512, bsrc0 + j * 4096);
        asm volatile("cp.async.commit_group;" ::: "memory");
        asm volatile("cp.async.wait_group 0;" ::: "memory");
    }
    __syncthreads();

    const uint32_t aBase = sbase +
        2u * (uint32_t)((wm * 64 + (lane & 15)) * LDAB + ((lane >> 4) << 3));

    for (int nh = 0; nh < nH; nh++) {
        float acc[4][4][4];
        #pragma unroll
        for (int i = 0; i < 4; i++)
            #pragma unroll
            for (int j = 0; j < 4; j++)
                #pragma unroll
                for (int q = 0; q < 4; q++) acc[i][j][q] = 0.f;

        #pragma unroll
        for (int ks = 0; ks < 8; ks++) {
            const int ka = ks * 16;
            const int s  = nh * 8 + ks;
            const int sn = (s + 1 < steps) ? s + 1 : s;
            // prefetch step sn into the other stage
            {
                const char* src = bsrc0 + (size_t)(sn >> 3) * WT_TILE_BYTES + (sn & 7) * 512;
                uint32_t dst = bring + ((s + 1) & 1) * 2048;
                #pragma unroll
                for (int j = 0; j < 4; j++)
                    cpasync16(dst + j * 512, src + j * 4096);
                asm volatile("cp.async.commit_group;" ::: "memory");
                asm volatile("cp.async.wait_group 1;" ::: "memory");
            }
            // consume current stage from smem
            uint4 bv[4];
            {
                const char* p = brd + (s & 1) * 2048;
                #pragma unroll
                for (int j = 0; j < 4; j++)
                    bv[j] = *(const uint4*)(p + j * 512);
            }

            unsigned ah[4][4];
            #pragma unroll
            for (int i = 0; i < 4; i++)
                ldsm_x4(ah[i], aBase + 2u * (uint32_t)(i * 16 * LDAB + ka));
            #pragma unroll
            for (int i = 0; i < 4; i++)
                #pragma unroll
                for (int j = 0; j < 4; j++)
                    mma_bf16(acc[i][j], ah[i], bv[j].x, bv[j].y);   // Ah Bh
            {
                unsigned al[4][4];
                #pragma unroll
                for (int i = 0; i < 4; i++)
                    ldsm_x4(al[i], aBase + 2u * (uint32_t)(i * 16 * LDAB + ka + 128));
                #pragma unroll
                for (int i = 0; i < 4; i++)
                    #pragma unroll
                    for (int j = 0; j < 4; j++)
                        mma_bf16(acc[i][j], al[i], bv[j].x, bv[j].y);   // Al Bh
            }
            #pragma unroll
            for (int i = 0; i < 4; i++)
                #pragma unroll
                for (int j = 0; j < 4; j++)
                    mma_bf16(acc[i][j], ah[i], bv[j].z, bv[j].w);   // Ah Bl
        }

        // ---- register epilogue (NPAD-padded outputs: no row guard) ----
        const int mode = (nh == 0) ? m0 : m1;
        const int cb = wn * 32 + 2 * (lane & 3);
        const int rb = row0 + wm * 64 + (lane >> 2);

        if (mode == 0) {
            float2 bvv[4];
            #pragma unroll
            for (int j = 0; j < 4; j++) bvv[j] = *(const float2*)&bias[cb + j * 8];
            char* outp = (char*)o0;
            #pragma unroll
            for (int i = 0; i < 4; i++) {
                char* p1 = outp + (size_t)(rb + i * 16) * 512;
                char* p2 = p1 + 8 * 512;
                #pragma unroll
                for (int j = 0; j < 4; j++) {
                    float* a = acc[i][j];
                    int c2 = (cb + j * 8) * 2;
                    unsigned hi, lo;
                    split2(fmaxf(a[0] + bvv[j].x, 0.f), fmaxf(a[1] + bvv[j].y, 0.f), hi, lo);
                    *(unsigned*)(p1 + c2) = hi;
                    *(unsigned*)(p1 + 256 + c2) = lo;
                    split2(fmaxf(a[2] + bvv[j].x, 0.f), fmaxf(a[3] + bvv[j].y, 0.f), hi, lo);
                    *(unsigned*)(p2 + c2) = hi;
                    *(unsigned*)(p2 + 256 + c2) = lo;
                }
            }
        } else if (mode == 1) {
            __half* out = (__half*)o0;
            #pragma unroll
            for (int i = 0; i < 4; i++) {
                size_t r1 = (size_t)(rb + i * 16) * 128;
                size_t r2 = r1 + 8 * 128;
                #pragma unroll
                for (int j = 0; j < 4; j++) {
                    float* a = acc[i][j];
                    int c = cb + j * 8;
                    *(__half2*)&out[r1 + c] = __floats2half2_rn(a[0], a[1]);
                    *(__half2*)&out[r2 + c] = __floats2half2_rn(a[2], a[3]);
                }
            }
        } else if (mode == 2) {
            float* out = (float*)o1;
            #pragma unroll
            for (int i = 0; i < 4; i++) {
                size_t r1 = (size_t)(rb + i * 16) * 128;
                size_t r2 = r1 + 8 * 128;
                #pragma unroll
                for (int j = 0; j < 4; j++) {
                    float* a = acc[i][j];
                    int c = cb + j * 8;
                    *(float2*)&out[r1 + c] = make_float2(a[0], a[1]);
                    *(float2*)&out[r2 + c] = make_float2(a[2], a[3]);
                }
            }
        } else {   // mode 3
            if (wn < 2) {
                __half* out = (__half*)o0;
                #pragma unroll
                for (int i = 0; i < 4; i++) {
                    size_t r1 = (size_t)(rb + i * 16) * 64;
                    size_t r2 = r1 + 8 * 64;
                    #pragma unroll
                    for (int j = 0; j < 4; j++) {
                        float* a = acc[i][j];
                        int c = cb + j * 8;
                        *(__half2*)&out[r1 + c] = __floats2half2_rn(a[0], a[1]);
                        *(__half2*)&out[r2 + c] = __floats2half2_rn(a[2], a[3]);
                    }
                }
            } else {
                float* out = (float*)o1;
                #pragma unroll
                for (int i = 0; i < 4; i++) {
                    size_t r1 = (size_t)(rb + i * 16) * 64;
                    size_t r2 = r1 + 8 * 64;
                    #pragma unroll
                    for (int j = 0; j < 4; j++) {
                        float* a = acc[i][j];
                        int c = cb + j * 8 - 64;
                        *(float2*)&out[r1 + c] = make_float2(a[0], a[1]);
                        *(float2*)&out[r2 + c] = make_float2(a[2], a[3]);
                    }
                }
            }
        }
    }
}

// ======================= LayerNorm (split in -> split out) =======================
__global__ __launch_bounds__(256) void k_ln(const char* __restrict__ in,
                                            char* __restrict__ out,
                                            const float* __restrict__ g,
                                            const float* __restrict__ b)
{
    int R    = blockIdx.x * 8 + (threadIdx.x >> 5);
    int lane = threadIdx.x & 31;
    float v[4];
    split_load_rm(in, R, lane, v);
    float s = v[0] + v[1] + v[2] + v[3];
    #pragma unroll
    for (int o = 16; o; o >>= 1) s += __shfl_xor_sync(0xffffffffu, s, o);
    float mean = s * (1.f / 128.f);
    float d0 = v[0] - mean, d1 = v[1] - mean, d2 = v[2] - mean, d3 = v[3] - mean;
    float ss = d0 * d0 + d1 * d1 + d2 * d2 + d3 * d3;
    #pragma unroll
    for (int o = 16; o; o >>= 1) ss += __shfl_xor_sync(0xffffffffu, ss, o);
    float inv = 1.f / (sqrtf(ss * (1.f / 127.f)) + 1e-6f);
    float4 gg = *(const float4*)&g[lane * 4];
    float4 bb = *(const float4*)&b[lane * 4];
    float o4[4];
    o4[0] = gg.x * d0 * inv + bb.x;
    o4[1] = gg.y * d1 * inv + bb.y;
    o4[2] = gg.z * d2 * inv + bb.z;
    o4[3] = gg.w * d3 * inv + bb.w;
    split_store_rm(out, R, lane, o4);
}

// ======================= GCN aggregate (fp16 gather) =======================
template <int OUT, int SPLIT>
__global__ __launch_bounds__(256) void k_agg(const __half* __restrict__ supn,
                                             const float* __restrict__ selfm,
                                             const float* __restrict__ bias,
                                             void* __restrict__ out)
{
    const int V = OUT / 32;
    int node = blockIdx.x * 8 + (threadIdx.x >> 5);
    int lane = threadIdx.x & 31;

    float acc[V];
    {
        const float* sr = selfm + (size_t)node * OUT + lane * V;
        #pragma unroll
        for (int i = 0; i < V; i++) acc[i] = sr[i] + bias[lane * V + i];
    }

    int e0 = g_rowptr[node], e1 = g_rowptr[node + 1];
    for (int eb = e0; eb < e1; eb += 32) {
        int rem = e1 - eb;
        int c = 0; float wv = 0.f;
        if (lane < rem) { c = g_ecol[eb + lane]; wv = g_eval[eb + lane]; }
        if (rem >= 32) {
            #pragma unroll 8
            for (int j = 0; j < 32; j++) {
                int   cj = __shfl_sync(0xffffffffu, c, j);
                float wj = __shfl_sync(0xffffffffu, wv, j);
                const __half* srow = supn + (size_t)cj * OUT + lane * V;
                if (V == 4) {
                    uint2 u = *(const uint2*)srow;
                    float2 f0 = __half22float2(*(const __half2*)&u.x);
                    float2 f1 = __half22float2(*(const __half2*)&u.y);
                    acc[0] = fmaf(wj, f0.x, acc[0]);
                    acc[1] = fmaf(wj, f0.y, acc[1]);
                    acc[2] = fmaf(wj, f1.x, acc[2]);
                    acc[3] = fmaf(wj, f1.y, acc[3]);
                } else {
                    uint32_t u = *(const uint32_t*)srow;
                    float2 f0 = __half22float2(*(const __half2*)&u);
                    acc[0] = fmaf(wj, f0.x, acc[0]);
                    acc[1] = fmaf(wj, f0.y, acc[1]);
                }
            }
        } else {
            for (int j = 0; j < rem; j++) {
                int   cj = __shfl_sync(0xffffffffu, c, j);
                float wj = __shfl_sync(0xffffffffu, wv, j);
                const __half* srow = supn + (size_t)cj * OUT + lane * V;
                if (V == 4) {
                    uint2 u = *(const uint2*)srow;
                    float2 f0 = __half22float2(*(const __half2*)&u.x);
                    float2 f1 = __half22float2(*(const __half2*)&u.y);
                    acc[0] = fmaf(wj, f0.x, acc[0]);
                    acc[1] = fmaf(wj, f0.y, acc[1]);
                    acc[2] = fmaf(wj, f1.x, acc[2]);
                    acc[3] = fmaf(wj, f1.y, acc[3]);
                } else {
                    uint32_t u = *(const uint32_t*)srow;
                    float2 f0 = __half22float2(*(const __half2*)&u);
                    acc[0] = fmaf(wj, f0.x, acc[0]);
                    acc[1] = fmaf(wj, f0.y, acc[1]);
                }
            }
        }
    }

    if (SPLIT) {
        float v[4];
        #pragma unroll
        for (int i = 0; i < 4; i++) v[i] = fmaxf(acc[i], 0.f);
        split_store_rm((char*)out, node, lane, v);
    } else {
        float* orow = (float*)out + (size_t)node * OUT + lane * V;
        #pragma unroll
        for (int i = 0; i < V; i++) orow[i] = fmaxf(acc[i], 0.f);
    }
}

// ======================= launch =======================
extern "C" void kernel_launch(void* const* d_in, const int* in_sizes, int n_in,
                              void* d_out, int out_size)
{
    const float* x    = (const float*)d_in[0];
    const int*   er   = (const int*)d_in[1];
    const int*   ec   = (const int*)d_in[2];
    const float* ev   = (const float*)d_in[3];
    const float* fc1w = (const float*)d_in[4];
    const float* fc1b = (const float*)d_in[5];
    const float* fc2w = (const float*)d_in[6];
    const float* fc2b = (const float*)d_in[7];
    const float* lng  = (const float*)d_in[8];
    const float* lnb  = (const float*)d_in[9];
    const float *wn[4], *wsf[4], *gb[4];
    for (int i = 0; i < 4; i++) {
        wn[i]  = (const float*)d_in[10 + 3 * i];
        wsf[i] = (const float*)d_in[11 + 3 * i];
        gb[i]  = (const float*)d_in[12 + 3 * i];
    }
    float* outp = (float*)d_out;

    char *s0, *s1;
    float* selfb;
    __half* supn;
    __nv_bfloat16* wt;
    cudaGetSymbolAddress((void**)&s0,    g_h0);
    cudaGetSymbolAddress((void**)&s1,    g_h1);
    cudaGetSymbolAddress((void**)&supn,  g_supn);
    cudaGetSymbolAddress((void**)&selfb, g_self);
    cudaGetSymbolAddress((void**)&wt,    g_wt);
    auto WT = [&](int t) { return wt + (size_t)t * 32768; };

    cudaFuncSetAttribute(k_mm, cudaFuncAttributeMaxDynamicSharedMemorySize, MM_SMEM);

    const int MT = (N_NODES + 127) / 128;   // 782

    k_wprep<<<dim3(128, 9), 128>>>(fc1w, fc2w, wn[0], wsf[0], wn[1], wsf[1],
                                   wn[2], wsf[2], wn[3], wsf[3], wt);            // 0
    k_xprep<<<NPAD / 8, 256>>>(x, s0);                                           // 1
    k_zero_rowptr<<<(NP1 + 255) / 256, 256>>>();                                 // 2
    k_mm<<<MT, 256, MM_SMEM>>>(s0, WT(0), fc1b, s1, 0, nullptr, 0, 1);           // 3 <- profiled
    k_hist<<<(N_EDGES + 255) / 256, 256>>>(er);                                  // 4
    k_scan1<<<NSCAN_BLOCKS, 1024>>>();                                           // 5
    k_scan2<<<1, 1>>>();                                                         // 6
    k_scan3<<<NSCAN_BLOCKS, 1024>>>();                                           // 7
    k_fill<<<(N_EDGES + 255) / 256, 256>>>(er, ec, ev);                          // 8
    k_mm<<<MT, 256, MM_SMEM>>>(s1, WT(1), fc2b, s0, 0, nullptr, 0, 1);           // 9
    k_ln<<<N_NODES / 8, 256>>>(s0, s1, lng, lnb);                                // 10

    char* cur = s1;
    char* nxt = s0;
    for (int l = 0; l < 3; l++) {
        k_mm<<<MT, 256, MM_SMEM>>>(cur, WT(2 + 2 * l), nullptr, supn, 1, selfb, 2, 2);
        k_agg<128, 1><<<N_NODES / 8, 256>>>(supn, selfb, gb[l], nxt);
        char* t = cur; cur = nxt; nxt = t;
    }

    k_mm<<<MT, 256, MM_SMEM>>>(cur, WT(8), nullptr, supn, 3, selfb, 3, 1);
    k_agg<64, 0><<<N_NODES / 8, 256>>>(supn, selfb, gb[3], outp);
}

// round 11
// speedup vs baseline: 1.0389x; 1.0389x over previous
#include <cuda_runtime.h>
#include <cuda_bf16.h>
#include <cuda_fp16.h>
#include <math.h>
#include <stdint.h>

#define N_NODES 100000
#define NPAD    100096
#define N_EDGES 3200000
#define NP1     100001
#define NSCAN_BLOCKS 98

#define LDAB 264                       // A smem row stride (bf16): [hi 128 | lo 128 | pad]
#define TM   64                        // rows per CTA tile
#define A_BYTES (TM * LDAB * 2)        // 33792
#define WT_TILE_BYTES 65536            // packed B tile: 16 nb x 8 ks x 512B

// ======================= device scratch =======================
__device__ int    g_rowptr[NP1];
__device__ int    g_bsum[128];
__device__ int    g_pos[N_NODES];
__device__ int    g_ecol[N_EDGES];
__device__ float  g_eval[N_EDGES];
__device__ float  g_h0[(size_t)NPAD * 128];   // split act buffer A (512B/row: hi|lo)
__device__ float  g_h1[(size_t)NPAD * 128];   // split act buffer B
__device__ __half g_supn[(size_t)NPAD * 128];
__device__ float  g_self[(size_t)NPAD * 128];
__device__ __nv_bfloat16 g_wt[9 * 32768];

// ======================= helpers =======================
__device__ __forceinline__ uint32_t smem_u32(const void* p) {
    uint32_t a;
    asm("{ .reg .u64 t; cvta.to.shared.u64 t, %1; cvt.u32.u64 %0, t; }" : "=r"(a) : "l"(p));
    return a;
}
__device__ __forceinline__ void ldsm_x4(unsigned* r, uint32_t addr) {
    asm volatile("ldmatrix.sync.aligned.m8n8.x4.shared.b16 {%0,%1,%2,%3}, [%4];"
        : "=r"(r[0]), "=r"(r[1]), "=r"(r[2]), "=r"(r[3]) : "r"(addr));
}
__device__ __forceinline__ void mma_bf16(float* c, const unsigned* a, unsigned b0, unsigned b1) {
    asm volatile("mma.sync.aligned.m16n8k16.row.col.f32.bf16.bf16.f32 "
        "{%0,%1,%2,%3}, {%4,%5,%6,%7}, {%8,%9}, {%0,%1,%2,%3};"
        : "+f"(c[0]), "+f"(c[1]), "+f"(c[2]), "+f"(c[3])
        : "r"(a[0]), "r"(a[1]), "r"(a[2]), "r"(a[3]), "r"(b0), "r"(b1));
}
__device__ __forceinline__ void cpasync16(uint32_t dst, const void* src) {
    asm volatile("cp.async.cg.shared.global [%0], [%1], 16;" :: "r"(dst), "l"(src));
}
__device__ __forceinline__ unsigned pk(float a, float b) {
    __nv_bfloat162 h = __floats2bfloat162_rn(a, b);
    return *(unsigned*)&h;
}
__device__ __forceinline__ void split2(float a0, float a1, unsigned& hi, unsigned& lo) {
    __nv_bfloat16 h0 = __float2bfloat16_rn(a0);
    __nv_bfloat16 h1 = __float2bfloat16_rn(a1);
    hi = pk(__bfloat162float(h0), __bfloat162float(h1));
    lo = pk(a0 - __bfloat162float(h0), a1 - __bfloat162float(h1));
}
__device__ __forceinline__ void split_store_rm(char* buf, int R, int lane, const float* v) {
    unsigned h01, h23, l01, l23;
    split2(v[0], v[1], h01, l01);
    split2(v[2], v[3], h23, l23);
    char* p = buf + (size_t)R * 512 + lane * 8;
    *(uint2*)p = make_uint2(h01, h23);
    *(uint2*)(p + 256) = make_uint2(l01, l23);
}
__device__ __forceinline__ void split_load_rm(const char* buf, int R, int lane, float* v) {
    const char* p = buf + (size_t)R * 512 + lane * 8;
    uint2 h = *(const uint2*)p;
    uint2 l = *(const uint2*)(p + 256);
    float2 fh0 = __bfloat1622float2(*(__nv_bfloat162*)&h.x);
    float2 fh1 = __bfloat1622float2(*(__nv_bfloat162*)&h.y);
    float2 fl0 = __bfloat1622float2(*(__nv_bfloat162*)&l.x);
    float2 fl1 = __bfloat1622float2(*(__nv_bfloat162*)&l.y);
    v[0] = fh0.x + fl0.x; v[1] = fh0.y + fl0.y;
    v[2] = fh1.x + fl1.x; v[3] = fh1.y + fl1.y;
}

// ======================= CSR build =======================
__global__ void k_zero_rowptr() {
    int i = blockIdx.x * blockDim.x + threadIdx.x;
    if (i < NP1) g_rowptr[i] = 0;
}
__global__ void k_hist(const int* __restrict__ rows) {
    int e = blockIdx.x * blockDim.x + threadIdx.x;
    if (e < N_EDGES) atomicAdd(&g_rowptr[rows[e] + 1], 1);
}
__global__ void k_scan1() {
    __shared__ int s[1024];
    int t = threadIdx.x, i = blockIdx.x * 1024 + t;
    int v = (i < NP1) ? g_rowptr[i] : 0;
    s[t] = v; __syncthreads();
    #pragma unroll
    for (int off = 1; off < 1024; off <<= 1) {
        int tv = 0;
        if (t >= off) tv = s[t - off];
        __syncthreads(); s[t] += tv; __syncthreads();
    }
    if (i < NP1) g_rowptr[i] = s[t];
    if (t == 1023) g_bsum[blockIdx.x] = s[1023];
}
__global__ void k_scan2() {
    int acc = 0;
    for (int b = 0; b < NSCAN_BLOCKS; b++) { acc += g_bsum[b]; g_bsum[b] = acc; }
}
__global__ void k_scan3() {
    int b = blockIdx.x;
    int i = b * 1024 + threadIdx.x;
    int add = b ? g_bsum[b - 1] : 0;
    if (i < NP1) {
        int v = g_rowptr[i] + add;
        g_rowptr[i] = v;
        if (i < N_NODES) g_pos[i] = v;
    }
}
__global__ void k_fill(const int* __restrict__ rows, const int* __restrict__ cols,
                       const float* __restrict__ vals) {
    int e = blockIdx.x * blockDim.x + threadIdx.x;
    if (e >= N_EDGES) return;
    int r = rows[e];
    int p = atomicAdd(&g_pos[r], 1);
    g_ecol[p] = cols[e];
    g_eval[p] = vals[e];
}

// ======================= weight prep: pack B in mma-fragment order ==============
__global__ void k_wprep(const float* __restrict__ fc1w, const float* __restrict__ fc2w,
                        const float* __restrict__ w0n, const float* __restrict__ w0s,
                        const float* __restrict__ w1n, const float* __restrict__ w1s,
                        const float* __restrict__ w2n, const float* __restrict__ w2s,
                        const float* __restrict__ w3n, const float* __restrict__ w3s,
                        __nv_bfloat16* __restrict__ wt)
{
    int t = blockIdx.y, n = blockIdx.x, k = threadIdx.x;
    float v;
    switch (t) {
        case 0: v = fc1w[n * 128 + k]; break;
        case 1: v = fc2w[n * 128 + k]; break;
        case 2: v = w0n[k * 128 + n]; break;
        case 3: v = w0s[k * 128 + n]; break;
        case 4: v = w1n[k * 128 + n]; break;
        case 5: v = w1s[k * 128 + n]; break;
        case 6: v = w2n[k * 128 + n]; break;
        case 7: v = w2s[k * 128 + n]; break;
        default: v = (n < 64) ? w3n[k * 64 + n] : w3s[k * 64 + (n - 64)]; break;
    }
    __nv_bfloat16 hi = __float2bfloat16_rn(v);
    __nv_bfloat16 lo = __float2bfloat16_rn(v - __bfloat162float(hi));

    int ks = k >> 4, kk = k & 15;
    int q, e;
    if (kk < 8) { q = kk >> 1; e = kk & 1; }
    else        { q = (kk - 8) >> 1; e = 2 + (kk & 1); }
    int nb = n >> 3, n7 = n & 7;
    char* base = (char*)wt + (size_t)t * WT_TILE_BYTES
               + ((nb * 8 + ks) * 512) + n7 * 64 + q * 16;
    *(__nv_bfloat16*)(base + e * 2)     = hi;
    *(__nv_bfloat16*)(base + 8 + e * 2) = lo;
}

// ======================= X prep: f32 -> split rows =======================
__global__ __launch_bounds__(256) void k_xprep(const float* __restrict__ X, char* __restrict__ dst) {
    int R = blockIdx.x * 8 + (threadIdx.x >> 5);
    int lane = threadIdx.x & 31;
    float v[4] = {0.f, 0.f, 0.f, 0.f};
    if (R < N_NODES) {
        float4 f = *(const float4*)&X[(size_t)R * 128 + lane * 4];
        v[0] = f.x; v[1] = f.y; v[2] = f.z; v[3] = f.w;
    }
    split_store_rm(dst, R, lane, v);
}

// ======================= bf16 GEMM: 64x128 CTA tile, 32x32 warp tile ============
// modes: 0 = bias+relu -> split rows o0 ; 1 = fp16 supn (ld128) ;
//        2 = f32 self (ld128) ; 3 = split64: wn<2 -> fp16 o0 (ld64), wn>=2 -> f32 o1 (ld64)
__global__ __launch_bounds__(256, 3) void k_mm(
    const char* __restrict__ Asp,
    const __nv_bfloat16* __restrict__ Bw,
    const float* __restrict__ bias,
    void* __restrict__ o0, int m0,
    void* __restrict__ o1, int m1,
    int nH)
{
    extern __shared__ __nv_bfloat16 As[];   // TM x LDAB

    const int tid = threadIdx.x, wid = tid >> 5, lane = tid & 31;
    const int wm = wid >> 2, wn = wid & 3;   // warp tile: 32 rows x 32 cols
    const int row0 = blockIdx.x * TM;
    const uint32_t sbase = smem_u32(As);

    // ---- prologue: cp.async pre-split A tile (32KB) ----
    {
        const char* gsrc = Asp + (size_t)row0 * 512;
        #pragma unroll
        for (int it = 0; it < 8; it++) {
            int i = tid + 256 * it;          // 2048 x 16B
            int r = i >> 5, c = i & 31;
            cpasync16(sbase + r * (LDAB * 2) + c * 16, gsrc + (size_t)i * 16);
        }
        asm volatile("cp.async.commit_group;" ::: "memory");
        asm volatile("cp.async.wait_group 0;" ::: "memory");
    }
    __syncthreads();

    const uint32_t aBase = sbase +
        2u * (uint32_t)((wm * 32 + (lane & 15)) * LDAB + ((lane >> 4) << 3));
    const char* bLane = (const char*)Bw + (lane >> 2) * 64 + (lane & 3) * 16;

    for (int nh = 0; nh < nH; nh++) {
        const char* Bt = bLane + (size_t)nh * WT_TILE_BYTES;

        float acc[2][4][4];
        #pragma unroll
        for (int i = 0; i < 2; i++)
            #pragma unroll
            for (int j = 0; j < 4; j++)
                #pragma unroll
                for (int q = 0; q < 4; q++) acc[i][j][q] = 0.f;

        #pragma unroll
        for (int ks = 0; ks < 8; ks++) {
            const int ka = ks * 16;
            uint4 bv[4];
            #pragma unroll
            for (int j = 0; j < 4; j++)
                bv[j] = *(const uint4*)(Bt + ((wn * 4 + j) * 8 + ks) * 512);

            unsigned ah[2][4];
            #pragma unroll
            for (int i = 0; i < 2; i++)
                ldsm_x4(ah[i], aBase + 2u * (uint32_t)(i * 16 * LDAB + ka));
            #pragma unroll
            for (int i = 0; i < 2; i++)
                #pragma unroll
                for (int j = 0; j < 4; j++)
                    mma_bf16(acc[i][j], ah[i], bv[j].x, bv[j].y);   // Ah Bh
            {
                unsigned al[2][4];
                #pragma unroll
                for (int i = 0; i < 2; i++)
                    ldsm_x4(al[i], aBase + 2u * (uint32_t)(i * 16 * LDAB + ka + 128));
                #pragma unroll
                for (int i = 0; i < 2; i++)
                    #pragma unroll
                    for (int j = 0; j < 4; j++)
                        mma_bf16(acc[i][j], al[i], bv[j].x, bv[j].y);   // Al Bh
            }
            #pragma unroll
            for (int i = 0; i < 2; i++)
                #pragma unroll
                for (int j = 0; j < 4; j++)
                    mma_bf16(acc[i][j], ah[i], bv[j].z, bv[j].w);   // Ah Bl
        }

        // ---- register epilogue (NPAD-padded outputs: no row guard) ----
        const int mode = (nh == 0) ? m0 : m1;
        const int cb = wn * 32 + 2 * (lane & 3);
        const int rb = row0 + wm * 32 + (lane >> 2);

        if (mode == 0) {
            float2 bvv[4];
            #pragma unroll
            for (int j = 0; j < 4; j++) bvv[j] = *(const float2*)&bias[cb + j * 8];
            char* outp = (char*)o0;
            #pragma unroll
            for (int i = 0; i < 2; i++) {
                char* p1 = outp + (size_t)(rb + i * 16) * 512;
                char* p2 = p1 + 8 * 512;
                #pragma unroll
                for (int j = 0; j < 4; j++) {
                    float* a = acc[i][j];
                    int c2 = (cb + j * 8) * 2;
                    unsigned hi, lo;
                    split2(fmaxf(a[0] + bvv[j].x, 0.f), fmaxf(a[1] + bvv[j].y, 0.f), hi, lo);
                    *(unsigned*)(p1 + c2) = hi;
                    *(unsigned*)(p1 + 256 + c2) = lo;
                    split2(fmaxf(a[2] + bvv[j].x, 0.f), fmaxf(a[3] + bvv[j].y, 0.f), hi, lo);
                    *(unsigned*)(p2 + c2) = hi;
                    *(unsigned*)(p2 + 256 + c2) = lo;
                }
            }
        } else if (mode == 1) {
            __half* out = (__half*)o0;
            #pragma unroll
            for (int i = 0; i < 2; i++) {
                size_t r1 = (size_t)(rb + i * 16) * 128;
                size_t r2 = r1 + 8 * 128;
                #pragma unroll
                for (int j = 0; j < 4; j++) {
                    float* a = acc[i][j];
                    int c = cb + j * 8;
                    *(__half2*)&out[r1 + c] = __floats2half2_rn(a[0], a[1]);
                    *(__half2*)&out[r2 + c] = __floats2half2_rn(a[2], a[3]);
                }
            }
        } else if (mode == 2) {
            float* out = (float*)o1;
            #pragma unroll
            for (int i = 0; i < 2; i++) {
                size_t r1 = (size_t)(rb + i * 16) * 128;
                size_t r2 = r1 + 8 * 128;
                #pragma unroll
                for (int j = 0; j < 4; j++) {
                    float* a = acc[i][j];
                    int c = cb + j * 8;
                    *(float2*)&out[r1 + c] = make_float2(a[0], a[1]);
                    *(float2*)&out[r2 + c] = make_float2(a[2], a[3]);
                }
            }
        } else {   // mode 3
            if (wn < 2) {
                __half* out = (__half*)o0;
                #pragma unroll
                for (int i = 0; i < 2; i++) {
                    size_t r1 = (size_t)(rb + i * 16) * 64;
                    size_t r2 = r1 + 8 * 64;
                    #pragma unroll
                    for (int j = 0; j < 4; j++) {
                        float* a = acc[i][j];
                        int c = cb + j * 8;
                        *(__half2*)&out[r1 + c] = __floats2half2_rn(a[0], a[1]);
                        *(__half2*)&out[r2 + c] = __floats2half2_rn(a[2], a[3]);
                    }
                }
            } else {
                float* out = (float*)o1;
                #pragma unroll
                for (int i = 0; i < 2; i++) {
                    size_t r1 = (size_t)(rb + i * 16) * 64;
                    size_t r2 = r1 + 8 * 64;
                    #pragma unroll
                    for (int j = 0; j < 4; j++) {
                        float* a = acc[i][j];
                        int c = cb + j * 8 - 64;
                        *(float2*)&out[r1 + c] = make_float2(a[0], a[1]);
                        *(float2*)&out[r2 + c] = make_float2(a[2], a[3]);
                    }
                }
            }
        }
    }
}

// ======================= LayerNorm (split in -> split out) =======================
__global__ __launch_bounds__(256) void k_ln(const char* __restrict__ in,
                                            char* __restrict__ out,
                                            const float* __restrict__ g,
                                            const float* __restrict__ b)
{
    int R    = blockIdx.x * 8 + (threadIdx.x >> 5);
    int lane = threadIdx.x & 31;
    float v[4];
    split_load_rm(in, R, lane, v);
    float s = v[0] + v[1] + v[2] + v[3];
    #pragma unroll
    for (int o = 16; o; o >>= 1) s += __shfl_xor_sync(0xffffffffu, s, o);
    float mean = s * (1.f / 128.f);
    float d0 = v[0] - mean, d1 = v[1] - mean, d2 = v[2] - mean, d3 = v[3] - mean;
    float ss = d0 * d0 + d1 * d1 + d2 * d2 + d3 * d3;
    #pragma unroll
    for (int o = 16; o; o >>= 1) ss += __shfl_xor_sync(0xffffffffu, ss, o);
    float inv = 1.f / (sqrtf(ss * (1.f / 127.f)) + 1e-6f);
    float4 gg = *(const float4*)&g[lane * 4];
    float4 bb = *(const float4*)&b[lane * 4];
    float o4[4];
    o4[0] = gg.x * d0 * inv + bb.x;
    o4[1] = gg.y * d1 * inv + bb.y;
    o4[2] = gg.z * d2 * inv + bb.z;
    o4[3] = gg.w * d3 * inv + bb.w;
    split_store_rm(out, R, lane, o4);
}

// ======================= GCN aggregate (fp16 gather) =======================
template <int OUT, int SPLIT>
__global__ __launch_bounds__(256) void k_agg(const __half* __restrict__ supn,
                                             const float* __restrict__ selfm,
                                             const float* __restrict__ bias,
                                             void* __restrict__ out)
{
    const int V = OUT / 32;
    int node = blockIdx.x * 8 + (threadIdx.x >> 5);
    int lane = threadIdx.x & 31;

    float acc[V];
    {
        const float* sr = selfm + (size_t)node * OUT + lane * V;
        #pragma unroll
        for (int i = 0; i < V; i++) acc[i] = sr[i] + bias[lane * V + i];
    }

    int e0 = g_rowptr[node], e1 = g_rowptr[node + 1];
    for (int eb = e0; eb < e1; eb += 32) {
        int rem = e1 - eb;
        int c = 0; float wv = 0.f;
        if (lane < rem) { c = g_ecol[eb + lane]; wv = g_eval[eb + lane]; }
        if (rem >= 32) {
            #pragma unroll 8
            for (int j = 0; j < 32; j++) {
                int   cj = __shfl_sync(0xffffffffu, c, j);
                float wj = __shfl_sync(0xffffffffu, wv, j);
                const __half* srow = supn + (size_t)cj * OUT + lane * V;
                if (V == 4) {
                    uint2 u = *(const uint2*)srow;
                    float2 f0 = __half22float2(*(const __half2*)&u.x);
                    float2 f1 = __half22float2(*(const __half2*)&u.y);
                    acc[0] = fmaf(wj, f0.x, acc[0]);
                    acc[1] = fmaf(wj, f0.y, acc[1]);
                    acc[2] = fmaf(wj, f1.x, acc[2]);
                    acc[3] = fmaf(wj, f1.y, acc[3]);
                } else {
                    uint32_t u = *(const uint32_t*)srow;
                    float2 f0 = __half22float2(*(const __half2*)&u);
                    acc[0] = fmaf(wj, f0.x, acc[0]);
                    acc[1] = fmaf(wj, f0.y, acc[1]);
                }
            }
        } else {
            for (int j = 0; j < rem; j++) {
                int   cj = __shfl_sync(0xffffffffu, c, j);
                float wj = __shfl_sync(0xffffffffu, wv, j);
                const __half* srow = supn + (size_t)cj * OUT + lane * V;
                if (V == 4) {
                    uint2 u = *(const uint2*)srow;
                    float2 f0 = __half22float2(*(const __half2*)&u.x);
                    float2 f1 = __half22float2(*(const __half2*)&u.y);
                    acc[0] = fmaf(wj, f0.x, acc[0]);
                    acc[1] = fmaf(wj, f0.y, acc[1]);
                    acc[2] = fmaf(wj, f1.x, acc[2]);
                    acc[3] = fmaf(wj, f1.y, acc[3]);
                } else {
                    uint32_t u = *(const uint32_t*)srow;
                    float2 f0 = __half22float2(*(const __half2*)&u);
                    acc[0] = fmaf(wj, f0.x, acc[0]);
                    acc[1] = fmaf(wj, f0.y, acc[1]);
                }
            }
        }
    }

    if (SPLIT) {
        float v[4];
        #pragma unroll
        for (int i = 0; i < 4; i++) v[i] = fmaxf(acc[i], 0.f);
        split_store_rm((char*)out, node, lane, v);
    } else {
        float* orow = (float*)out + (size_t)node * OUT + lane * V;
        #pragma unroll
        for (int i = 0; i < V; i++) orow[i] = fmaxf(acc[i], 0.f);
    }
}

// ======================= launch =======================
extern "C" void kernel_launch(void* const* d_in, const int* in_sizes, int n_in,
                              void* d_out, int out_size)
{
    const float* x    = (const float*)d_in[0];
    const int*   er   = (const int*)d_in[1];
    const int*   ec   = (const int*)d_in[2];
    const float* ev   = (const float*)d_in[3];
    const float* fc1w = (const float*)d_in[4];
    const float* fc1b = (const float*)d_in[5];
    const float* fc2w = (const float*)d_in[6];
    const float* fc2b = (const float*)d_in[7];
    const float* lng  = (const float*)d_in[8];
    const float* lnb  = (const float*)d_in[9];
    const float *wn[4], *wsf[4], *gb[4];
    for (int i = 0; i < 4; i++) {
        wn[i]  = (const float*)d_in[10 + 3 * i];
        wsf[i] = (const float*)d_in[11 + 3 * i];
        gb[i]  = (const float*)d_in[12 + 3 * i];
    }
    float* outp = (float*)d_out;

    char *s0, *s1;
    float* selfb;
    __half* supn;
    __nv_bfloat16* wt;
    cudaGetSymbolAddress((void**)&s0,    g_h0);
    cudaGetSymbolAddress((void**)&s1,    g_h1);
    cudaGetSymbolAddress((void**)&supn,  g_supn);
    cudaGetSymbolAddress((void**)&selfb, g_self);
    cudaGetSymbolAddress((void**)&wt,    g_wt);
    auto WT = [&](int t) { return wt + (size_t)t * 32768; };

    const int MT = NPAD / TM;   // 1564

    k_wprep<<<dim3(128, 9), 128>>>(fc1w, fc2w, wn[0], wsf[0], wn[1], wsf[1],
                                   wn[2], wsf[2], wn[3], wsf[3], wt);            // 0
    k_xprep<<<NPAD / 8, 256>>>(x, s0);                                           // 1
    k_zero_rowptr<<<(NP1 + 255) / 256, 256>>>();                                 // 2
    k_mm<<<MT, 256, A_BYTES>>>(s0, WT(0), fc1b, s1, 0, nullptr, 0, 1);           // 3 <- profiled
    k_hist<<<(N_EDGES + 255) / 256, 256>>>(er);                                  // 4
    k_scan1<<<NSCAN_BLOCKS, 1024>>>();                                           // 5
    k_scan2<<<1, 1>>>();                                                         // 6
    k_scan3<<<NSCAN_BLOCKS, 1024>>>();                                           // 7
    k_fill<<<(N_EDGES + 255) / 256, 256>>>(er, ec, ev);                          // 8
    k_mm<<<MT, 256, A_BYTES>>>(s1, WT(1), fc2b, s0, 0, nullptr, 0, 1);           // 9
    k_ln<<<N_NODES / 8, 256>>>(s0, s1, lng, lnb);                                // 10

    char* cur = s1;
    char* nxt = s0;
    for (int l = 0; l < 3; l++) {
        k_mm<<<MT, 256, A_BYTES>>>(cur, WT(2 + 2 * l), nullptr, supn, 1, selfb, 2, 2);
        k_agg<128, 1><<<N_NODES / 8, 256>>>(supn, selfb, gb[l], nxt);
        char* t = cur; cur = nxt; nxt = t;
    }

    k_mm<<<MT, 256, A_BYTES>>>(cur, WT(8), nullptr, supn, 3, selfb, 3, 1);
    k_agg<64, 0><<<N_NODES / 8, 256>>>(supn, selfb, gb[3], outp);
}

// round 12
// speedup vs baseline: 1.1070x; 1.0655x over previous
#include <cuda_runtime.h>
#include <cuda_fp16.h>
#include <math.h>
#include <stdint.h>

#define N_NODES 100000
#define NPAD    100096
#define N_EDGES 3200000
#define NP1     100001
#define NSCAN_BLOCKS 98

#define LDAB 264                       // A smem row stride (fp16): [hi 128 | lo 128 | pad]
#define TM   64                        // rows per CTA tile
#define A_BYTES (TM * LDAB * 2)        // 33792
#define WT_TILE_BYTES 32768            // packed fp16 B tile: 16 nb x 8 ks x 256B

// ======================= device scratch =======================
__device__ int    g_rowptr[NP1];
__device__ int    g_bsum[128];
__device__ int    g_pos[N_NODES];
__device__ int    g_ecol[N_EDGES];
__device__ float  g_eval[N_EDGES];
__device__ float  g_h0[(size_t)NPAD * 128];   // split act buffer A (512B/row: hi|lo fp16)
__device__ float  g_h1[(size_t)NPAD * 128];   // split act buffer B
__device__ __half g_supn[(size_t)NPAD * 128];
__device__ float  g_self[(size_t)NPAD * 128];
__device__ __half g_wt[9 * 16384];            // 9 x 32KB packed fp16 tiles

// ======================= helpers =======================
__device__ __forceinline__ uint32_t smem_u32(const void* p) {
    uint32_t a;
    asm("{ .reg .u64 t; cvta.to.shared.u64 t, %1; cvt.u32.u64 %0, t; }" : "=r"(a) : "l"(p));
    return a;
}
__device__ __forceinline__ void ldsm_x4(unsigned* r, uint32_t addr) {
    asm volatile("ldmatrix.sync.aligned.m8n8.x4.shared.b16 {%0,%1,%2,%3}, [%4];"
        : "=r"(r[0]), "=r"(r[1]), "=r"(r[2]), "=r"(r[3]) : "r"(addr));
}
__device__ __forceinline__ void mma_fp16(float* c, const unsigned* a, unsigned b0, unsigned b1) {
    asm volatile("mma.sync.aligned.m16n8k16.row.col.f32.f16.f16.f32 "
        "{%0,%1,%2,%3}, {%4,%5,%6,%7}, {%8,%9}, {%0,%1,%2,%3};"
        : "+f"(c[0]), "+f"(c[1]), "+f"(c[2]), "+f"(c[3])
        : "r"(a[0]), "r"(a[1]), "r"(a[2]), "r"(a[3]), "r"(b0), "r"(b1));
}
__device__ __forceinline__ void cpasync16(uint32_t dst, const void* src) {
    asm volatile("cp.async.cg.shared.global [%0], [%1], 16;" :: "r"(dst), "l"(src));
}
// split pair into exact fp16 hi (packed) + fp16 lo (packed)
__device__ __forceinline__ void split2(float a0, float a1, unsigned& hi, unsigned& lo) {
    __half h0 = __float2half_rn(a0);
    __half h1 = __float2half_rn(a1);
    __half2 hp = __halves2half2(h0, h1);
    hi = *(unsigned*)&hp;
    __half2 lp = __floats2half2_rn(a0 - __half2float(h0), a1 - __half2float(h1));
    lo = *(unsigned*)&lp;
}
__device__ __forceinline__ void split_store_rm(char* buf, int R, int lane, const float* v) {
    unsigned h01, h23, l01, l23;
    split2(v[0], v[1], h01, l01);
    split2(v[2], v[3], h23, l23);
    char* p = buf + (size_t)R * 512 + lane * 8;
    *(uint2*)p = make_uint2(h01, h23);
    *(uint2*)(p + 256) = make_uint2(l01, l23);
}
__device__ __forceinline__ void split_load_rm(const char* buf, int R, int lane, float* v) {
    const char* p = buf + (size_t)R * 512 + lane * 8;
    uint2 h = *(const uint2*)p;
    uint2 l = *(const uint2*)(p + 256);
    float2 fh0 = __half22float2(*(__half2*)&h.x);
    float2 fh1 = __half22float2(*(__half2*)&h.y);
    float2 fl0 = __half22float2(*(__half2*)&l.x);
    float2 fl1 = __half22float2(*(__half2*)&l.y);
    v[0] = fh0.x + fl0.x; v[1] = fh0.y + fl0.y;
    v[2] = fh1.x + fl1.x; v[3] = fh1.y + fl1.y;
}

// ======================= CSR build =======================
__global__ void k_zero_rowptr() {
    int i = blockIdx.x * blockDim.x + threadIdx.x;
    if (i < NP1) g_rowptr[i] = 0;
}
__global__ void k_hist(const int* __restrict__ rows) {
    int e = blockIdx.x * blockDim.x + threadIdx.x;
    if (e < N_EDGES) atomicAdd(&g_rowptr[rows[e] + 1], 1);
}
__global__ void k_scan1() {
    __shared__ int s[1024];
    int t = threadIdx.x, i = blockIdx.x * 1024 + t;
    int v = (i < NP1) ? g_rowptr[i] : 0;
    s[t] = v; __syncthreads();
    #pragma unroll
    for (int off = 1; off < 1024; off <<= 1) {
        int tv = 0;
        if (t >= off) tv = s[t - off];
        __syncthreads(); s[t] += tv; __syncthreads();
    }
    if (i < NP1) g_rowptr[i] = s[t];
    if (t == 1023) g_bsum[blockIdx.x] = s[1023];
}
__global__ void k_scan2() {
    int acc = 0;
    for (int b = 0; b < NSCAN_BLOCKS; b++) { acc += g_bsum[b]; g_bsum[b] = acc; }
}
__global__ void k_scan3() {
    int b = blockIdx.x;
    int i = b * 1024 + threadIdx.x;
    int add = b ? g_bsum[b - 1] : 0;
    if (i < NP1) {
        int v = g_rowptr[i] + add;
        g_rowptr[i] = v;
        if (i < N_NODES) g_pos[i] = v;
    }
}
__global__ void k_fill(const int* __restrict__ rows, const int* __restrict__ cols,
                       const float* __restrict__ vals) {
    int e = blockIdx.x * blockDim.x + threadIdx.x;
    if (e >= N_EDGES) return;
    int r = rows[e];
    int p = atomicAdd(&g_pos[r], 1);
    g_ecol[p] = cols[e];
    g_eval[p] = vals[e];
}

// ======================= weight prep: pack fp16 B in mma-fragment order =========
// Tile (32KB): nb(16) x ks(8) -> 256B block; inside: n7(8) x 32B; q(4) x 8B; e(4) x 2B
__global__ void k_wprep(const float* __restrict__ fc1w, const float* __restrict__ fc2w,
                        const float* __restrict__ w0n, const float* __restrict__ w0s,
                        const float* __restrict__ w1n, const float* __restrict__ w1s,
                        const float* __restrict__ w2n, const float* __restrict__ w2s,
                        const float* __restrict__ w3n, const float* __restrict__ w3s,
                        __half* __restrict__ wt)
{
    int t = blockIdx.y, n = blockIdx.x, k = threadIdx.x;
    float v;
    switch (t) {
        case 0: v = fc1w[n * 128 + k]; break;
        case 1: v = fc2w[n * 128 + k]; break;
        case 2: v = w0n[k * 128 + n]; break;
        case 3: v = w0s[k * 128 + n]; break;
        case 4: v = w1n[k * 128 + n]; break;
        case 5: v = w1s[k * 128 + n]; break;
        case 6: v = w2n[k * 128 + n]; break;
        case 7: v = w2s[k * 128 + n]; break;
        default: v = (n < 64) ? w3n[k * 64 + n] : w3s[k * 64 + (n - 64)]; break;
    }
    int ks = k >> 4, kk = k & 15;
    int q, e;
    if (kk < 8) { q = kk >> 1; e = kk & 1; }
    else        { q = (kk - 8) >> 1; e = 2 + (kk & 1); }
    int nb = n >> 3, n7 = n & 7;
    char* base = (char*)wt + (size_t)t * WT_TILE_BYTES
               + ((nb * 8 + ks) * 256) + n7 * 32 + q * 8;
    *(__half*)(base + e * 2) = __float2half_rn(v);
}

// ======================= X prep: f32 -> split fp16 rows =======================
__global__ __launch_bounds__(256) void k_xprep(const float* __restrict__ X, char* __restrict__ dst) {
    int R = blockIdx.x * 8 + (threadIdx.x >> 5);
    int lane = threadIdx.x & 31;
    float v[4] = {0.f, 0.f, 0.f, 0.f};
    if (R < N_NODES) {
        float4 f = *(const float4*)&X[(size_t)R * 128 + lane * 4];
        v[0] = f.x; v[1] = f.y; v[2] = f.z; v[3] = f.w;
    }
    split_store_rm(dst, R, lane, v);
}

// ======================= fp16 GEMM (2-term A-split): 64x128 CTA, 32x32 warp =====
// modes: 0 = bias+relu -> split rows o0 ; 1 = fp16 supn (ld128) ;
//        2 = f32 self (ld128) ; 3 = split64: wn<2 -> fp16 o0 (ld64), wn>=2 -> f32 o1 (ld64)
__global__ __launch_bounds__(256, 3) void k_mm(
    const char* __restrict__ Asp,
    const __half* __restrict__ Bw,
    const float* __restrict__ bias,
    void* __restrict__ o0, int m0,
    void* __restrict__ o1, int m1,
    int nH)
{
    extern __shared__ __half As[];   // TM x LDAB

    const int tid = threadIdx.x, wid = tid >> 5, lane = tid & 31;
    const int wm = wid >> 2, wn = wid & 3;   // warp tile: 32 rows x 32 cols
    const int row0 = blockIdx.x * TM;
    const uint32_t sbase = smem_u32(As);

    // ---- prologue: cp.async pre-split A tile (32KB) ----
    {
        const char* gsrc = Asp + (size_t)row0 * 512;
        #pragma unroll
        for (int it = 0; it < 8; it++) {
            int i = tid + 256 * it;          // 2048 x 16B
            int r = i >> 5, c = i & 31;
            cpasync16(sbase + r * (LDAB * 2) + c * 16, gsrc + (size_t)i * 16);
        }
        asm volatile("cp.async.commit_group;" ::: "memory");
        asm volatile("cp.async.wait_group 0;" ::: "memory");
    }
    __syncthreads();

    const uint32_t aBase = sbase +
        2u * (uint32_t)((wm * 32 + (lane & 15)) * LDAB + ((lane >> 4) << 3));
    const char* bLane = (const char*)Bw + (lane >> 2) * 32 + (lane & 3) * 8;

    for (int nh = 0; nh < nH; nh++) {
        const char* Bt = bLane + (size_t)nh * WT_TILE_BYTES;

        float acc[2][4][4];
        #pragma unroll
        for (int i = 0; i < 2; i++)
            #pragma unroll
            for (int j = 0; j < 4; j++)
                #pragma unroll
                for (int q = 0; q < 4; q++) acc[i][j][q] = 0.f;

        #pragma unroll
        for (int ks = 0; ks < 8; ks++) {
            const int ka = ks * 16;
            uint2 bv[4];
            #pragma unroll
            for (int j = 0; j < 4; j++)
                bv[j] = *(const uint2*)(Bt + ((wn * 4 + j) * 8 + ks) * 256);

            unsigned ah[2][4];
            #pragma unroll
            for (int i = 0; i < 2; i++)
                ldsm_x4(ah[i], aBase + 2u * (uint32_t)(i * 16 * LDAB + ka));
            #pragma unroll
            for (int i = 0; i < 2; i++)
                #pragma unroll
                for (int j = 0; j < 4; j++)
                    mma_fp16(acc[i][j], ah[i], bv[j].x, bv[j].y);   // Ah B
            {
                unsigned al[2][4];
                #pragma unroll
                for (int i = 0; i < 2; i++)
                    ldsm_x4(al[i], aBase + 2u * (uint32_t)(i * 16 * LDAB + ka + 128));
                #pragma unroll
                for (int i = 0; i < 2; i++)
                    #pragma unroll
                    for (int j = 0; j < 4; j++)
                        mma_fp16(acc[i][j], al[i], bv[j].x, bv[j].y);   // Al B
            }
        }

        // ---- register epilogue (NPAD-padded outputs: no row guard) ----
        const int mode = (nh == 0) ? m0 : m1;
        const int cb = wn * 32 + 2 * (lane & 3);
        const int rb = row0 + wm * 32 + (lane >> 2);

        if (mode == 0) {
            float2 bvv[4];
            #pragma unroll
            for (int j = 0; j < 4; j++) bvv[j] = *(const float2*)&bias[cb + j * 8];
            char* outp = (char*)o0;
            #pragma unroll
            for (int i = 0; i < 2; i++) {
                char* p1 = outp + (size_t)(rb + i * 16) * 512;
                char* p2 = p1 + 8 * 512;
                #pragma unroll
                for (int j = 0; j < 4; j++) {
                    float* a = acc[i][j];
                    int c2 = (cb + j * 8) * 2;
                    unsigned hi, lo;
                    split2(fmaxf(a[0] + bvv[j].x, 0.f), fmaxf(a[1] + bvv[j].y, 0.f), hi, lo);
                    *(unsigned*)(p1 + c2) = hi;
                    *(unsigned*)(p1 + 256 + c2) = lo;
                    split2(fmaxf(a[2] + bvv[j].x, 0.f), fmaxf(a[3] + bvv[j].y, 0.f), hi, lo);
                    *(unsigned*)(p2 + c2) = hi;
                    *(unsigned*)(p2 + 256 + c2) = lo;
                }
            }
        } else if (mode == 1) {
            __half* out = (__half*)o0;
            #pragma unroll
            for (int i = 0; i < 2; i++) {
                size_t r1 = (size_t)(rb + i * 16) * 128;
                size_t r2 = r1 + 8 * 128;
                #pragma unroll
                for (int j = 0; j < 4; j++) {
                    float* a = acc[i][j];
                    int c = cb + j * 8;
                    *(__half2*)&out[r1 + c] = __floats2half2_rn(a[0], a[1]);
                    *(__half2*)&out[r2 + c] = __floats2half2_rn(a[2], a[3]);
                }
            }
        } else if (mode == 2) {
            float* out = (float*)o1;
            #pragma unroll
            for (int i = 0; i < 2; i++) {
                size_t r1 = (size_t)(rb + i * 16) * 128;
                size_t r2 = r1 + 8 * 128;
                #pragma unroll
                for (int j = 0; j < 4; j++) {
                    float* a = acc[i][j];
                    int c = cb + j * 8;
                    *(float2*)&out[r1 + c] = make_float2(a[0], a[1]);
                    *(float2*)&out[r2 + c] = make_float2(a[2], a[3]);
                }
            }
        } else {   // mode 3
            if (wn < 2) {
                __half* out = (__half*)o0;
                #pragma unroll
                for (int i = 0; i < 2; i++) {
                    size_t r1 = (size_t)(rb + i * 16) * 64;
                    size_t r2 = r1 + 8 * 64;
                    #pragma unroll
                    for (int j = 0; j < 4; j++) {
                        float* a = acc[i][j];
                        int c = cb + j * 8;
                        *(__half2*)&out[r1 + c] = __floats2half2_rn(a[0], a[1]);
                        *(__half2*)&out[r2 + c] = __floats2half2_rn(a[2], a[3]);
                    }
                }
            } else {
                float* out = (float*)o1;
                #pragma unroll
                for (int i = 0; i < 2; i++) {
                    size_t r1 = (size_t)(rb + i * 16) * 64;
                    size_t r2 = r1 + 8 * 64;
                    #pragma unroll
                    for (int j = 0; j < 4; j++) {
                        float* a = acc[i][j];
                        int c = cb + j * 8 - 64;
                        *(float2*)&out[r1 + c] = make_float2(a[0], a[1]);
                        *(float2*)&out[r2 + c] = make_float2(a[2], a[3]);
                    }
                }
            }
        }
    }
}

// ======================= LayerNorm (split in -> split out) =======================
__global__ __launch_bounds__(256) void k_ln(const char* __restrict__ in,
                                            char* __restrict__ out,
                                            const float* __restrict__ g,
                                            const float* __restrict__ b)
{
    int R    = blockIdx.x * 8 + (threadIdx.x >> 5);
    int lane = threadIdx.x & 31;
    float v[4];
    split_load_rm(in, R, lane, v);
    float s = v[0] + v[1] + v[2] + v[3];
    #pragma unroll
    for (int o = 16; o; o >>= 1) s += __shfl_xor_sync(0xffffffffu, s, o);
    float mean = s * (1.f / 128.f);
    float d0 = v[0] - mean, d1 = v[1] - mean, d2 = v[2] - mean, d3 = v[3] - mean;
    float ss = d0 * d0 + d1 * d1 + d2 * d2 + d3 * d3;
    #pragma unroll
    for (int o = 16; o; o >>= 1) ss += __shfl_xor_sync(0xffffffffu, ss, o);
    float inv = 1.f / (sqrtf(ss * (1.f / 127.f)) + 1e-6f);
    float4 gg = *(const float4*)&g[lane * 4];
    float4 bb = *(const float4*)&b[lane * 4];
    float o4[4];
    o4[0] = gg.x * d0 * inv + bb.x;
    o4[1] = gg.y * d1 * inv + bb.y;
    o4[2] = gg.z * d2 * inv + bb.z;
    o4[3] = gg.w * d3 * inv + bb.w;
    split_store_rm(out, R, lane, o4);
}

// ======================= GCN aggregate (fp16 gather) =======================
template <int OUT, int SPLIT>
__global__ __launch_bounds__(256) void k_agg(const __half* __restrict__ supn,
                                             const float* __restrict__ selfm,
                                             const float* __restrict__ bias,
                                             void* __restrict__ out)
{
    const int V = OUT / 32;
    int node = blockIdx.x * 8 + (threadIdx.x >> 5);
    int lane = threadIdx.x & 31;

    float acc[V];
    {
        const float* sr = selfm + (size_t)node * OUT + lane * V;
        #pragma unroll
        for (int i = 0; i < V; i++) acc[i] = sr[i] + bias[lane * V + i];
    }

    int e0 = g_rowptr[node], e1 = g_rowptr[node + 1];
    for (int eb = e0; eb < e1; eb += 32) {
        int rem = e1 - eb;
        int c = 0; float wv = 0.f;
        if (lane < rem) { c = g_ecol[eb + lane]; wv = g_eval[eb + lane]; }
        if (rem >= 32) {
            #pragma unroll 8
            for (int j = 0; j < 32; j++) {
                int   cj = __shfl_sync(0xffffffffu, c, j);
                float wj = __shfl_sync(0xffffffffu, wv, j);
                const __half* srow = supn + (size_t)cj * OUT + lane * V;
                if (V == 4) {
                    uint2 u = *(const uint2*)srow;
                    float2 f0 = __half22float2(*(const __half2*)&u.x);
                    float2 f1 = __half22float2(*(const __half2*)&u.y);
                    acc[0] = fmaf(wj, f0.x, acc[0]);
                    acc[1] = fmaf(wj, f0.y, acc[1]);
                    acc[2] = fmaf(wj, f1.x, acc[2]);
                    acc[3] = fmaf(wj, f1.y, acc[3]);
                } else {
                    uint32_t u = *(const uint32_t*)srow;
                    float2 f0 = __half22float2(*(const __half2*)&u);
                    acc[0] = fmaf(wj, f0.x, acc[0]);
                    acc[1] = fmaf(wj, f0.y, acc[1]);
                }
            }
        } else {
            for (int j = 0; j < rem; j++) {
                int   cj = __shfl_sync(0xffffffffu, c, j);
                float wj = __shfl_sync(0xffffffffu, wv, j);
                const __half* srow = supn + (size_t)cj * OUT + lane * V;
                if (V == 4) {
                    uint2 u = *(const uint2*)srow;
                    float2 f0 = __half22float2(*(const __half2*)&u.x);
                    float2 f1 = __half22float2(*(const __half2*)&u.y);
                    acc[0] = fmaf(wj, f0.x, acc[0]);
                    acc[1] = fmaf(wj, f0.y, acc[1]);
                    acc[2] = fmaf(wj, f1.x, acc[2]);
                    acc[3] = fmaf(wj, f1.y, acc[3]);
                } else {
                    uint32_t u = *(const uint32_t*)srow;
                    float2 f0 = __half22float2(*(const __half2*)&u);
                    acc[0] = fmaf(wj, f0.x, acc[0]);
                    acc[1] = fmaf(wj, f0.y, acc[1]);
                }
            }
        }
    }

    if (SPLIT) {
        float v[4];
        #pragma unroll
        for (int i = 0; i < 4; i++) v[i] = fmaxf(acc[i], 0.f);
        split_store_rm((char*)out, node, lane, v);
    } else {
        float* orow = (float*)out + (size_t)node * OUT + lane * V;
        #pragma unroll
        for (int i = 0; i < V; i++) orow[i] = fmaxf(acc[i], 0.f);
    }
}

// ======================= launch =======================
extern "C" void kernel_launch(void* const* d_in, const int* in_sizes, int n_in,
                              void* d_out, int out_size)
{
    const float* x    = (const float*)d_in[0];
    const int*   er   = (const int*)d_in[1];
    const int*   ec   = (const int*)d_in[2];
    const float* ev   = (const float*)d_in[3];
    const float* fc1w = (const float*)d_in[4];
    const float* fc1b = (const float*)d_in[5];
    const float* fc2w = (const float*)d_in[6];
    const float* fc2b = (const float*)d_in[7];
    const float* lng  = (const float*)d_in[8];
    const float* lnb  = (const float*)d_in[9];
    const float *wn[4], *wsf[4], *gb[4];
    for (int i = 0; i < 4; i++) {
        wn[i]  = (const float*)d_in[10 + 3 * i];
        wsf[i] = (const float*)d_in[11 + 3 * i];
        gb[i]  = (const float*)d_in[12 + 3 * i];
    }
    float* outp = (float*)d_out;

    char *s0, *s1;
    float* selfb;
    __half* supn;
    __half* wt;
    cudaGetSymbolAddress((void**)&s0,    g_h0);
    cudaGetSymbolAddress((void**)&s1,    g_h1);
    cudaGetSymbolAddress((void**)&supn,  g_supn);
    cudaGetSymbolAddress((void**)&selfb, g_self);
    cudaGetSymbolAddress((void**)&wt,    g_wt);
    auto WT = [&](int t) { return wt + (size_t)t * 16384; };

    const int MT = NPAD / TM;   // 1564

    k_wprep<<<dim3(128, 9), 128>>>(fc1w, fc2w, wn[0], wsf[0], wn[1], wsf[1],
                                   wn[2], wsf[2], wn[3], wsf[3], wt);            // 0
    k_xprep<<<NPAD / 8, 256>>>(x, s0);                                           // 1
    k_zero_rowptr<<<(NP1 + 255) / 256, 256>>>();                                 // 2
    k_mm<<<MT, 256, A_BYTES>>>(s0, WT(0), fc1b, s1, 0, nullptr, 0, 1);           // 3 <- profiled
    k_hist<<<(N_EDGES + 255) / 256, 256>>>(er);                                  // 4
    k_scan1<<<NSCAN_BLOCKS, 1024>>>();                                           // 5
    k_scan2<<<1, 1>>>();                                                         // 6
    k_scan3<<<NSCAN_BLOCKS, 1024>>>();                                           // 7
    k_fill<<<(N_EDGES + 255) / 256, 256>>>(er, ec, ev);                          // 8
    k_mm<<<MT, 256, A_BYTES>>>(s1, WT(1), fc2b, s0, 0, nullptr, 0, 1);           // 9
    k_ln<<<N_NODES / 8, 256>>>(s0, s1, lng, lnb);                                // 10

    char* cur = s1;
    char* nxt = s0;
    for (int l = 0; l < 3; l++) {
        k_mm<<<MT, 256, A_BYTES>>>(cur, WT(2 + 2 * l), nullptr, supn, 1, selfb, 2, 2);
        k_agg<128, 1><<<N_NODES / 8, 256>>>(supn, selfb, gb[l], nxt);
        char* t = cur; cur = nxt; nxt = t;
    }

    k_mm<<<MT, 256, A_BYTES>>>(cur, WT(8), nullptr, supn, 3, selfb, 3, 1);
    k_agg<64, 0><<<N_NODES / 8, 256>>>(supn, selfb, gb[3], outp);
}

// round 13
// speedup vs baseline: 1.1866x; 1.0719x over previous
#include <cuda_runtime.h>
#include <cuda_fp16.h>
#include <math.h>
#include <stdint.h>

#define N_NODES 100000
#define NPAD    100096
#define N_EDGES 3200000
#define NP1     100001
#define NSCAN_BLOCKS 98

#define LDA  136                       // A smem row stride (fp16): 128 + 8 pad
#define TM   64                        // rows per CTA tile
#define A_BYTES (TM * LDA * 2)         // 17408
#define WT_TILE_BYTES 32768            // packed fp16 B tile: 16 nb x 8 ks x 256B

// ======================= device scratch =======================
__device__ int    g_rowptr[NP1];
__device__ int    g_bsum[128];
__device__ int    g_pos[N_NODES];
__device__ int    g_ecol[N_EDGES];
__device__ float  g_eval[N_EDGES];
__device__ __half g_h0[(size_t)NPAD * 128];   // fp16 activation buffer A
__device__ __half g_h1[(size_t)NPAD * 128];   // fp16 activation buffer B
__device__ __half g_supn[(size_t)NPAD * 128];
__device__ float  g_self[(size_t)NPAD * 128];
__device__ __half g_wt[9 * 16384];            // 9 x 32KB packed fp16 tiles

// ======================= helpers =======================
__device__ __forceinline__ uint32_t smem_u32(const void* p) {
    uint32_t a;
    asm("{ .reg .u64 t; cvta.to.shared.u64 t, %1; cvt.u32.u64 %0, t; }" : "=r"(a) : "l"(p));
    return a;
}
__device__ __forceinline__ void ldsm_x4(unsigned* r, uint32_t addr) {
    asm volatile("ldmatrix.sync.aligned.m8n8.x4.shared.b16 {%0,%1,%2,%3}, [%4];"
        : "=r"(r[0]), "=r"(r[1]), "=r"(r[2]), "=r"(r[3]) : "r"(addr));
}
__device__ __forceinline__ void mma_fp16(float* c, const unsigned* a, unsigned b0, unsigned b1) {
    asm volatile("mma.sync.aligned.m16n8k16.row.col.f32.f16.f16.f32 "
        "{%0,%1,%2,%3}, {%4,%5,%6,%7}, {%8,%9}, {%0,%1,%2,%3};"
        : "+f"(c[0]), "+f"(c[1]), "+f"(c[2]), "+f"(c[3])
        : "r"(a[0]), "r"(a[1]), "r"(a[2]), "r"(a[3]), "r"(b0), "r"(b1));
}
__device__ __forceinline__ void cpasync16(uint32_t dst, const void* src) {
    asm volatile("cp.async.cg.shared.global [%0], [%1], 16;" :: "r"(dst), "l"(src));
}

// ======================= CSR build =======================
__global__ void k_zero_rowptr() {
    int i = blockIdx.x * blockDim.x + threadIdx.x;
    if (i < NP1) g_rowptr[i] = 0;
}
__global__ void k_hist(const int* __restrict__ rows) {
    int e = blockIdx.x * blockDim.x + threadIdx.x;
    if (e < N_EDGES) atomicAdd(&g_rowptr[rows[e] + 1], 1);
}
__global__ void k_scan1() {
    __shared__ int s[1024];
    int t = threadIdx.x, i = blockIdx.x * 1024 + t;
    int v = (i < NP1) ? g_rowptr[i] : 0;
    s[t] = v; __syncthreads();
    #pragma unroll
    for (int off = 1; off < 1024; off <<= 1) {
        int tv = 0;
        if (t >= off) tv = s[t - off];
        __syncthreads(); s[t] += tv; __syncthreads();
    }
    if (i < NP1) g_rowptr[i] = s[t];
    if (t == 1023) g_bsum[blockIdx.x] = s[1023];
}
__global__ void k_scan2() {
    int acc = 0;
    for (int b = 0; b < NSCAN_BLOCKS; b++) { acc += g_bsum[b]; g_bsum[b] = acc; }
}
__global__ void k_scan3() {
    int b = blockIdx.x;
    int i = b * 1024 + threadIdx.x;
    int add = b ? g_bsum[b - 1] : 0;
    if (i < NP1) {
        int v = g_rowptr[i] + add;
        g_rowptr[i] = v;
        if (i < N_NODES) g_pos[i] = v;
    }
}
__global__ void k_fill(const int* __restrict__ rows, const int* __restrict__ cols,
                       const float* __restrict__ vals) {
    int e = blockIdx.x * blockDim.x + threadIdx.x;
    if (e >= N_EDGES) return;
    int r = rows[e];
    int p = atomicAdd(&g_pos[r], 1);
    g_ecol[p] = cols[e];
    g_eval[p] = vals[e];
}

// ======================= weight prep: pack fp16 B in mma-fragment order =========
__global__ void k_wprep(const float* __restrict__ fc1w, const float* __restrict__ fc2w,
                        const float* __restrict__ w0n, const float* __restrict__ w0s,
                        const float* __restrict__ w1n, const float* __restrict__ w1s,
                        const float* __restrict__ w2n, const float* __restrict__ w2s,
                        const float* __restrict__ w3n, const float* __restrict__ w3s,
                        __half* __restrict__ wt)
{
    int t = blockIdx.y, n = blockIdx.x, k = threadIdx.x;
    float v;
    switch (t) {
        case 0: v = fc1w[n * 128 + k]; break;
        case 1: v = fc2w[n * 128 + k]; break;
        case 2: v = w0n[k * 128 + n]; break;
        case 3: v = w0s[k * 128 + n]; break;
        case 4: v = w1n[k * 128 + n]; break;
        case 5: v = w1s[k * 128 + n]; break;
        case 6: v = w2n[k * 128 + n]; break;
        case 7: v = w2s[k * 128 + n]; break;
        default: v = (n < 64) ? w3n[k * 64 + n] : w3s[k * 64 + (n - 64)]; break;
    }
    int ks = k >> 4, kk = k & 15;
    int q, e;
    if (kk < 8) { q = kk >> 1; e = kk & 1; }
    else        { q = (kk - 8) >> 1; e = 2 + (kk & 1); }
    int nb = n >> 3, n7 = n & 7;
    char* base = (char*)wt + (size_t)t * WT_TILE_BYTES
               + ((nb * 8 + ks) * 256) + n7 * 32 + q * 8;
    *(__half*)(base + e * 2) = __float2half_rn(v);
}

// ======================= X prep: f32 -> fp16 rows =======================
__global__ __launch_bounds__(256) void k_xprep(const float* __restrict__ X, __half* __restrict__ dst) {
    int R = blockIdx.x * 8 + (threadIdx.x >> 5);
    int lane = threadIdx.x & 31;
    float4 v = make_float4(0.f, 0.f, 0.f, 0.f);
    if (R < N_NODES) v = *(const float4*)&X[(size_t)R * 128 + lane * 4];
    __half2 a = __floats2half2_rn(v.x, v.y);
    __half2 b = __floats2half2_rn(v.z, v.w);
    *(uint2*)&dst[(size_t)R * 128 + lane * 4] = make_uint2(*(unsigned*)&a, *(unsigned*)&b);
}

// ======================= fp16 GEMM (single pass): 64x128 CTA, 32x32 warp ========
// modes: 0 = bias+relu -> fp16 rows ; 1 = fp16 supn (ld128) ;
//        2 = f32 self (ld128) ; 3 = split64: wn<2 -> fp16 o0 (ld64), wn>=2 -> f32 o1 (ld64)
__global__ __launch_bounds__(256, 4) void k_mm(
    const __half* __restrict__ Asp,
    const __half* __restrict__ Bw,
    const float* __restrict__ bias,
    void* __restrict__ o0, int m0,
    void* __restrict__ o1, int m1,
    int nH)
{
    extern __shared__ __half As[];   // TM x LDA

    const int tid = threadIdx.x, wid = tid >> 5, lane = tid & 31;
    const int wm = wid >> 2, wn = wid & 3;   // warp tile: 32 rows x 32 cols
    const int row0 = blockIdx.x * TM;
    const uint32_t sbase = smem_u32(As);

    // ---- prologue: cp.async fp16 A tile (16KB) ----
    {
        const char* gsrc = (const char*)(Asp + (size_t)row0 * 128);
        #pragma unroll
        for (int it = 0; it < 4; it++) {
            int i = tid + 256 * it;          // 1024 x 16B
            int r = i >> 4, c = i & 15;
            cpasync16(sbase + r * (LDA * 2) + c * 16, gsrc + (size_t)i * 16);
        }
        asm volatile("cp.async.commit_group;" ::: "memory");
        asm volatile("cp.async.wait_group 0;" ::: "memory");
    }
    __syncthreads();

    const uint32_t aBase = sbase +
        2u * (uint32_t)((wm * 32 + (lane & 15)) * LDA + ((lane >> 4) << 3));
    const char* bLane = (const char*)Bw + (lane >> 2) * 32 + (lane & 3) * 8;

    for (int nh = 0; nh < nH; nh++) {
        const char* Bt = bLane + (size_t)nh * WT_TILE_BYTES;

        float acc[2][4][4];
        #pragma unroll
        for (int i = 0; i < 2; i++)
            #pragma unroll
            for (int j = 0; j < 4; j++)
                #pragma unroll
                for (int q = 0; q < 4; q++) acc[i][j][q] = 0.f;

        #pragma unroll
        for (int ks = 0; ks < 8; ks++) {
            const int ka = ks * 16;
            uint2 bv[4];
            #pragma unroll
            for (int j = 0; j < 4; j++)
                bv[j] = *(const uint2*)(Bt + ((wn * 4 + j) * 8 + ks) * 256);

            unsigned ah[2][4];
            #pragma unroll
            for (int i = 0; i < 2; i++)
                ldsm_x4(ah[i], aBase + 2u * (uint32_t)(i * 16 * LDA + ka));
            #pragma unroll
            for (int i = 0; i < 2; i++)
                #pragma unroll
                for (int j = 0; j < 4; j++)
                    mma_fp16(acc[i][j], ah[i], bv[j].x, bv[j].y);
        }

        // ---- register epilogue (NPAD-padded outputs: no row guard) ----
        const int mode = (nh == 0) ? m0 : m1;
        const int cb = wn * 32 + 2 * (lane & 3);
        const int rb = row0 + wm * 32 + (lane >> 2);

        if (mode == 0) {
            float2 bvv[4];
            #pragma unroll
            for (int j = 0; j < 4; j++) bvv[j] = *(const float2*)&bias[cb + j * 8];
            __half* out = (__half*)o0;
            #pragma unroll
            for (int i = 0; i < 2; i++) {
                size_t r1 = (size_t)(rb + i * 16) * 128;
                size_t r2 = r1 + 8 * 128;
                #pragma unroll
                for (int j = 0; j < 4; j++) {
                    float* a = acc[i][j];
                    int c = cb + j * 8;
                    *(__half2*)&out[r1 + c] = __floats2half2_rn(fmaxf(a[0] + bvv[j].x, 0.f),
                                                                fmaxf(a[1] + bvv[j].y, 0.f));
                    *(__half2*)&out[r2 + c] = __floats2half2_rn(fmaxf(a[2] + bvv[j].x, 0.f),
                                                                fmaxf(a[3] + bvv[j].y, 0.f));
                }
            }
        } else if (mode == 1) {
            __half* out = (__half*)o0;
            #pragma unroll
            for (int i = 0; i < 2; i++) {
                size_t r1 = (size_t)(rb + i * 16) * 128;
                size_t r2 = r1 + 8 * 128;
                #pragma unroll
                for (int j = 0; j < 4; j++) {
                    float* a = acc[i][j];
                    int c = cb + j * 8;
                    *(__half2*)&out[r1 + c] = __floats2half2_rn(a[0], a[1]);
                    *(__half2*)&out[r2 + c] = __floats2half2_rn(a[2], a[3]);
                }
            }
        } else if (mode == 2) {
            float* out = (float*)o1;
            #pragma unroll
            for (int i = 0; i < 2; i++) {
                size_t r1 = (size_t)(rb + i * 16) * 128;
                size_t r2 = r1 + 8 * 128;
                #pragma unroll
                for (int j = 0; j < 4; j++) {
                    float* a = acc[i][j];
                    int c = cb + j * 8;
                    *(float2*)&out[r1 + c] = make_float2(a[0], a[1]);
                    *(float2*)&out[r2 + c] = make_float2(a[2], a[3]);
                }
            }
        } else {   // mode 3
            if (wn < 2) {
                __half* out = (__half*)o0;
                #pragma unroll
                for (int i = 0; i < 2; i++) {
                    size_t r1 = (size_t)(rb + i * 16) * 64;
                    size_t r2 = r1 + 8 * 64;
                    #pragma unroll
                    for (int j = 0; j < 4; j++) {
                        float* a = acc[i][j];
                        int c = cb + j * 8;
                        *(__half2*)&out[r1 + c] = __floats2half2_rn(a[0], a[1]);
                        *(__half2*)&out[r2 + c] = __floats2half2_rn(a[2], a[3]);
                    }
                }
            } else {
                float* out = (float*)o1;
                #pragma unroll
                for (int i = 0; i < 2; i++) {
                    size_t r1 = (size_t)(rb + i * 16) * 64;
                    size_t r2 = r1 + 8 * 64;
                    #pragma unroll
                    for (int j = 0; j < 4; j++) {
                        float* a = acc[i][j];
                        int c = cb + j * 8 - 64;
                        *(float2*)&out[r1 + c] = make_float2(a[0], a[1]);
                        *(float2*)&out[r2 + c] = make_float2(a[2], a[3]);
                    }
                }
            }
        }
    }
}

// ======================= LayerNorm (fp16 in -> fp16 out) =======================
__global__ __launch_bounds__(256) void k_ln(const __half* __restrict__ in,
                                            __half* __restrict__ out,
                                            const float* __restrict__ g,
                                            const float* __restrict__ b)
{
    int R    = blockIdx.x * 8 + (threadIdx.x >> 5);
    int lane = threadIdx.x & 31;
    uint2 u = *(const uint2*)&in[(size_t)R * 128 + lane * 4];
    float2 f0 = __half22float2(*(__half2*)&u.x);
    float2 f1 = __half22float2(*(__half2*)&u.y);
    float v0 = f0.x, v1 = f0.y, v2 = f1.x, v3 = f1.y;
    float s = v0 + v1 + v2 + v3;
    #pragma unroll
    for (int o = 16; o; o >>= 1) s += __shfl_xor_sync(0xffffffffu, s, o);
    float mean = s * (1.f / 128.f);
    float d0 = v0 - mean, d1 = v1 - mean, d2 = v2 - mean, d3 = v3 - mean;
    float ss = d0 * d0 + d1 * d1 + d2 * d2 + d3 * d3;
    #pragma unroll
    for (int o = 16; o; o >>= 1) ss += __shfl_xor_sync(0xffffffffu, ss, o);
    float inv = 1.f / (sqrtf(ss * (1.f / 127.f)) + 1e-6f);
    float4 gg = *(const float4*)&g[lane * 4];
    float4 bb = *(const float4*)&b[lane * 4];
    __half2 o0 = __floats2half2_rn(gg.x * d0 * inv + bb.x, gg.y * d1 * inv + bb.y);
    __half2 o1 = __floats2half2_rn(gg.z * d2 * inv + bb.z, gg.w * d3 * inv + bb.w);
    *(uint2*)&out[(size_t)R * 128 + lane * 4] = make_uint2(*(unsigned*)&o0, *(unsigned*)&o1);
}

// ======================= GCN aggregate (fp16 gather) =======================
// HOUT=1: relu -> fp16 rows (OUT=128). HOUT=0: relu -> f32 rows.
template <int OUT, int HOUT>
__global__ __launch_bounds__(256) void k_agg(const __half* __restrict__ supn,
                                             const float* __restrict__ selfm,
                                             const float* __restrict__ bias,
                                             void* __restrict__ out)
{
    const int V = OUT / 32;
    int node = blockIdx.x * 8 + (threadIdx.x >> 5);
    int lane = threadIdx.x & 31;

    float acc[V];
    {
        const float* sr = selfm + (size_t)node * OUT + lane * V;
        #pragma unroll
        for (int i = 0; i < V; i++) acc[i] = sr[i] + bias[lane * V + i];
    }

    int e0 = g_rowptr[node], e1 = g_rowptr[node + 1];
    for (int eb = e0; eb < e1; eb += 32) {
        int rem = e1 - eb;
        int c = 0; float wv = 0.f;
        if (lane < rem) { c = g_ecol[eb + lane]; wv = g_eval[eb + lane]; }
        if (rem >= 32) {
            #pragma unroll 8
            for (int j = 0; j < 32; j++) {
                int   cj = __shfl_sync(0xffffffffu, c, j);
                float wj = __shfl_sync(0xffffffffu, wv, j);
                const __half* srow = supn + (size_t)cj * OUT + lane * V;
                if (V == 4) {
                    uint2 u = *(const uint2*)srow;
                    float2 f0 = __half22float2(*(const __half2*)&u.x);
                    float2 f1 = __half22float2(*(const __half2*)&u.y);
                    acc[0] = fmaf(wj, f0.x, acc[0]);
                    acc[1] = fmaf(wj, f0.y, acc[1]);
                    acc[2] = fmaf(wj, f1.x, acc[2]);
                    acc[3] = fmaf(wj, f1.y, acc[3]);
                } else {
                    uint32_t u = *(const uint32_t*)srow;
                    float2 f0 = __half22float2(*(const __half2*)&u);
                    acc[0] = fmaf(wj, f0.x, acc[0]);
                    acc[1] = fmaf(wj, f0.y, acc[1]);
                }
            }
        } else {
            for (int j = 0; j < rem; j++) {
                int   cj = __shfl_sync(0xffffffffu, c, j);
                float wj = __shfl_sync(0xffffffffu, wv, j);
                const __half* srow = supn + (size_t)cj * OUT + lane * V;
                if (V == 4) {
                    uint2 u = *(const uint2*)srow;
                    float2 f0 = __half22float2(*(const __half2*)&u.x);
                    float2 f1 = __half22float2(*(const __half2*)&u.y);
                    acc[0] = fmaf(wj, f0.x, acc[0]);
                    acc[1] = fmaf(wj, f0.y, acc[1]);
                    acc[2] = fmaf(wj, f1.x, acc[2]);
                    acc[3] = fmaf(wj, f1.y, acc[3]);
                } else {
                    uint32_t u = *(const uint32_t*)srow;
                    float2 f0 = __half22float2(*(const __half2*)&u);
                    acc[0] = fmaf(wj, f0.x, acc[0]);
                    acc[1] = fmaf(wj, f0.y, acc[1]);
                }
            }
        }
    }

    if (HOUT) {
        __half* orow = (__half*)out + (size_t)node * OUT + lane * V;
        __half2 a = __floats2half2_rn(fmaxf(acc[0], 0.f), fmaxf(acc[1], 0.f));
        __half2 b = __floats2half2_rn(fmaxf(acc[2], 0.f), fmaxf(acc[3], 0.f));
        *(uint2*)orow = make_uint2(*(unsigned*)&a, *(unsigned*)&b);
    } else {
        float* orow = (float*)out + (size_t)node * OUT + lane * V;
        #pragma unroll
        for (int i = 0; i < V; i++) orow[i] = fmaxf(acc[i], 0.f);
    }
}

// ======================= launch =======================
extern "C" void kernel_launch(void* const* d_in, const int* in_sizes, int n_in,
                              void* d_out, int out_size)
{
    const float* x    = (const float*)d_in[0];
    const int*   er   = (const int*)d_in[1];
    const int*   ec   = (const int*)d_in[2];
    const float* ev   = (const float*)d_in[3];
    const float* fc1w = (const float*)d_in[4];
    const float* fc1b = (const float*)d_in[5];
    const float* fc2w = (const float*)d_in[6];
    const float* fc2b = (const float*)d_in[7];
    const float* lng  = (const float*)d_in[8];
    const float* lnb  = (const float*)d_in[9];
    const float *wn[4], *wsf[4], *gb[4];
    for (int i = 0; i < 4; i++) {
        wn[i]  = (const float*)d_in[10 + 3 * i];
        wsf[i] = (const float*)d_in[11 + 3 * i];
        gb[i]  = (const float*)d_in[12 + 3 * i];
    }
    float* outp = (float*)d_out;

    __half *s0, *s1, *supn, *wt;
    float* selfb;
    cudaGetSymbolAddress((void**)&s0,    g_h0);
    cudaGetSymbolAddress((void**)&s1,    g_h1);
    cudaGetSymbolAddress((void**)&supn,  g_supn);
    cudaGetSymbolAddress((void**)&selfb, g_self);
    cudaGetSymbolAddress((void**)&wt,    g_wt);
    auto WT = [&](int t) { return wt + (size_t)t * 16384; };

    const int MT = NPAD / TM;   // 1564

    k_wprep<<<dim3(128, 9), 128>>>(fc1w, fc2w, wn[0], wsf[0], wn[1], wsf[1],
                                   wn[2], wsf[2], wn[3], wsf[3], wt);            // 0
    k_xprep<<<NPAD / 8, 256>>>(x, s0);                                           // 1
    k_zero_rowptr<<<(NP1 + 255) / 256, 256>>>();                                 // 2
    k_mm<<<MT, 256, A_BYTES>>>(s0, WT(0), fc1b, s1, 0, nullptr, 0, 1);           // 3 <- profiled
    k_hist<<<(N_EDGES + 255) / 256, 256>>>(er);                                  // 4
    k_scan1<<<NSCAN_BLOCKS, 1024>>>();                                           // 5
    k_scan2<<<1, 1>>>();                                                         // 6
    k_scan3<<<NSCAN_BLOCKS, 1024>>>();                                           // 7
    k_fill<<<(N_EDGES + 255) / 256, 256>>>(er, ec, ev);                          // 8
    k_mm<<<MT, 256, A_BYTES>>>(s1, WT(1), fc2b, s0, 0, nullptr, 0, 1);           // 9
    k_ln<<<N_NODES / 8, 256>>>(s0, s1, lng, lnb);                                // 10

    __half* cur = s1;
    __half* nxt = s0;
    for (int l = 0; l < 3; l++) {
        k_mm<<<MT, 256, A_BYTES>>>(cur, WT(2 + 2 * l), nullptr, supn, 1, selfb, 2, 2);
        k_agg<128, 1><<<N_NODES / 8, 256>>>(supn, selfb, gb[l], nxt);
        __half* t = cur; cur = nxt; nxt = t;
    }

    k_mm<<<MT, 256, A_BYTES>>>(cur, WT(8), nullptr, supn, 3, selfb, 3, 1);
    k_agg<64, 0><<<N_NODES / 8, 256>>>(supn, selfb, gb[3], outp);
}

// round 14
// speedup vs baseline: 1.3582x; 1.1446x over previous
#include <cuda_runtime.h>
#include <cuda_fp16.h>
#include <math.h>
#include <stdint.h>

#define N_NODES 100000
#define NPAD    100096
#define N_EDGES 3200000
#define NP1     100001
#define NSCAN_BLOCKS 98

#define LDA  136                       // A smem row stride (fp16): 128 + 8 pad
#define TM   64                        // rows per CTA tile
#define A_BYTES (TM * LDA * 2)         // 17408
#define WT_TILE_BYTES 32768            // packed fp16 B tile: 8 ks x 8 pair x 512B
#define MM_SMEM (A_BYTES + WT_TILE_BYTES)   // 50176

// ======================= device scratch =======================
__device__ int    g_rowptr[NP1];
__device__ int    g_bsum[128];
__device__ int    g_pos[N_NODES];
__device__ int    g_ecol[N_EDGES];
__device__ float  g_eval[N_EDGES];
__device__ __half g_h0[(size_t)NPAD * 128];
__device__ __half g_h1[(size_t)NPAD * 128];
__device__ __half g_supn[(size_t)NPAD * 128];
__device__ float  g_self[(size_t)NPAD * 128];
__device__ __half g_wt[9 * 16384];

// ======================= helpers =======================
__device__ __forceinline__ uint32_t smem_u32(const void* p) {
    uint32_t a;
    asm("{ .reg .u64 t; cvta.to.shared.u64 t, %1; cvt.u32.u64 %0, t; }" : "=r"(a) : "l"(p));
    return a;
}
__device__ __forceinline__ void ldsm_x4(unsigned* r, uint32_t addr) {
    asm volatile("ldmatrix.sync.aligned.m8n8.x4.shared.b16 {%0,%1,%2,%3}, [%4];"
        : "=r"(r[0]), "=r"(r[1]), "=r"(r[2]), "=r"(r[3]) : "r"(addr));
}
__device__ __forceinline__ uint4 lds128(uint32_t addr) {
    uint4 r;
    asm volatile("ld.shared.v4.b32 {%0,%1,%2,%3}, [%4];"
        : "=r"(r.x), "=r"(r.y), "=r"(r.z), "=r"(r.w) : "r"(addr));
    return r;
}
__device__ __forceinline__ void mma_fp16(float* c, const unsigned* a, unsigned b0, unsigned b1) {
    asm volatile("mma.sync.aligned.m16n8k16.row.col.f32.f16.f16.f32 "
        "{%0,%1,%2,%3}, {%4,%5,%6,%7}, {%8,%9}, {%0,%1,%2,%3};"
        : "+f"(c[0]), "+f"(c[1]), "+f"(c[2]), "+f"(c[3])
        : "r"(a[0]), "r"(a[1]), "r"(a[2]), "r"(a[3]), "r"(b0), "r"(b1));
}
__device__ __forceinline__ void cpasync16(uint32_t dst, const void* src) {
    asm volatile("cp.async.cg.shared.global [%0], [%1], 16;" :: "r"(dst), "l"(src));
}

// ======================= CSR build =======================
__global__ void k_zero_rowptr() {
    int i = blockIdx.x * blockDim.x + threadIdx.x;
    if (i < NP1) g_rowptr[i] = 0;
}
__global__ void k_hist(const int* __restrict__ rows) {
    int e = blockIdx.x * blockDim.x + threadIdx.x;
    if (e < N_EDGES) atomicAdd(&g_rowptr[rows[e] + 1], 1);
}
__global__ void k_scan1() {
    __shared__ int s[1024];
    int t = threadIdx.x, i = blockIdx.x * 1024 + t;
    int v = (i < NP1) ? g_rowptr[i] : 0;
    s[t] = v; __syncthreads();
    #pragma unroll
    for (int off = 1; off < 1024; off <<= 1) {
        int tv = 0;
        if (t >= off) tv = s[t - off];
        __syncthreads(); s[t] += tv; __syncthreads();
    }
    if (i < NP1) g_rowptr[i] = s[t];
    if (t == 1023) g_bsum[blockIdx.x] = s[1023];
}
__global__ void k_scan2() {
    int acc = 0;
    for (int b = 0; b < NSCAN_BLOCKS; b++) { acc += g_bsum[b]; g_bsum[b] = acc; }
}
__global__ void k_scan3() {
    int b = blockIdx.x;
    int i = b * 1024 + threadIdx.x;
    int add = b ? g_bsum[b - 1] : 0;
    if (i < NP1) {
        int v = g_rowptr[i] + add;
        g_rowptr[i] = v;
        if (i < N_NODES) g_pos[i] = v;
    }
}
__global__ void k_fill(const int* __restrict__ rows, const int* __restrict__ cols,
                       const float* __restrict__ vals) {
    int e = blockIdx.x * blockDim.x + threadIdx.x;
    if (e >= N_EDGES) return;
    int r = rows[e];
    int p = atomicAdd(&g_pos[r], 1);
    g_ecol[p] = cols[e];
    g_eval[p] = vals[e];
}

// ======================= weight prep: pack fp16 B, j-pair-contiguous ============
// addr = t*WT + (ks*8 + (nb>>1))*512 + n7*64 + q*16 + (nb&1)*8 + e*2
__global__ void k_wprep(const float* __restrict__ fc1w, const float* __restrict__ fc2w,
                        const float* __restrict__ w0n, const float* __restrict__ w0s,
                        const float* __restrict__ w1n, const float* __restrict__ w1s,
                        const float* __restrict__ w2n, const float* __restrict__ w2s,
                        const float* __restrict__ w3n, const float* __restrict__ w3s,
                        __half* __restrict__ wt)
{
    int t = blockIdx.y, n = blockIdx.x, k = threadIdx.x;
    float v;
    switch (t) {
        case 0: v = fc1w[n * 128 + k]; break;
        case 1: v = fc2w[n * 128 + k]; break;
        case 2: v = w0n[k * 128 + n]; break;
        case 3: v = w0s[k * 128 + n]; break;
        case 4: v = w1n[k * 128 + n]; break;
        case 5: v = w1s[k * 128 + n]; break;
        case 6: v = w2n[k * 128 + n]; break;
        case 7: v = w2s[k * 128 + n]; break;
        default: v = (n < 64) ? w3n[k * 64 + n] : w3s[k * 64 + (n - 64)]; break;
    }
    int ks = k >> 4, kk = k & 15;
    int q, e;
    if (kk < 8) { q = kk >> 1; e = kk & 1; }
    else        { q = (kk - 8) >> 1; e = 2 + (kk & 1); }
    int nb = n >> 3, n7 = n & 7;
    char* base = (char*)wt + (size_t)t * WT_TILE_BYTES
               + ((ks * 8 + (nb >> 1)) * 512) + n7 * 64 + q * 16 + (nb & 1) * 8;
    *(__half*)(base + e * 2) = __float2half_rn(v);
}

// ======================= X prep: f32 -> fp16 rows =======================
__global__ __launch_bounds__(256) void k_xprep(const float* __restrict__ X, __half* __restrict__ dst) {
    int R = blockIdx.x * 8 + (threadIdx.x >> 5);
    int lane = threadIdx.x & 31;
    float4 v = make_float4(0.f, 0.f, 0.f, 0.f);
    if (R < N_NODES) v = *(const float4*)&X[(size_t)R * 128 + lane * 4];
    __half2 a = __floats2half2_rn(v.x, v.y);
    __half2 b = __floats2half2_rn(v.z, v.w);
    *(uint2*)&dst[(size_t)R * 128 + lane * 4] = make_uint2(*(unsigned*)&a, *(unsigned*)&b);
}

// ======================= fp16 GEMM: all-smem mainloop ==========================
// modes: 0 = bias+relu -> fp16 o0 (ld128) ; 1 = fp16 o0 (ld128) ;
//        2 = f32 o0 (ld128) ; 3 = split64: wn<2 -> fp16 o0 (ld64), wn>=2 -> f32 o1 (ld64)
__global__ __launch_bounds__(256, 4) void k_mm(
    const __half* __restrict__ Asp,
    const __half* __restrict__ Bw,
    const float* __restrict__ bias,
    void* __restrict__ o0, void* __restrict__ o1, int mode)
{
    extern __shared__ __half As[];   // A: TM x LDA ; B tile at +A_BYTES

    const int tid = threadIdx.x, wid = tid >> 5, lane = tid & 31;
    const int wm = wid >> 2, wn = wid & 3;   // warp tile: 32 rows x 32 cols
    const int row0 = blockIdx.x * TM;
    const uint32_t sbase = smem_u32(As);

    // ---- prologue: cp.async A (16KB) + full B tile (32KB) ----
    {
        const char* gA = (const char*)(Asp + (size_t)row0 * 128);
        #pragma unroll
        for (int it = 0; it < 4; it++) {
            int i = tid + 256 * it;          // 1024 x 16B
            int r = i >> 4, c = i & 15;
            cpasync16(sbase + r * (LDA * 2) + c * 16, gA + (size_t)i * 16);
        }
        const char* gB = (const char*)Bw;
        #pragma unroll
        for (int it = 0; it < 8; it++) {
            int i = tid + 256 * it;          // 2048 x 16B
            cpasync16(sbase + A_BYTES + i * 16, gB + (size_t)i * 16);
        }
        asm volatile("cp.async.commit_group;" ::: "memory");
        asm volatile("cp.async.wait_group 0;" ::: "memory");
    }
    __syncthreads();

    const uint32_t aBase = sbase +
        2u * (uint32_t)((wm * 32 + (lane & 15)) * LDA + ((lane >> 4) << 3));
    const uint32_t bBase = sbase + A_BYTES + (wn * 2) * 512 + lane * 16;

    float acc[2][4][4];
    #pragma unroll
    for (int i = 0; i < 2; i++)
        #pragma unroll
        for (int j = 0; j < 4; j++)
            #pragma unroll
            for (int q = 0; q < 4; q++) acc[i][j][q] = 0.f;

    #pragma unroll
    for (int ks = 0; ks < 8; ks++) {
        const int ka = ks * 16;
        uint4 u0 = lds128(bBase + (ks * 8 + 0) * 512);   // j = 0,1
        uint4 u1 = lds128(bBase + (ks * 8 + 1) * 512);   // j = 2,3

        unsigned ah[2][4];
        #pragma unroll
        for (int i = 0; i < 2; i++)
            ldsm_x4(ah[i], aBase + 2u * (uint32_t)(i * 16 * LDA + ka));
        #pragma unroll
        for (int i = 0; i < 2; i++) {
            mma_fp16(acc[i][0], ah[i], u0.x, u0.y);
            mma_fp16(acc[i][1], ah[i], u0.z, u0.w);
            mma_fp16(acc[i][2], ah[i], u1.x, u1.y);
            mma_fp16(acc[i][3], ah[i], u1.z, u1.w);
        }
    }

    // ---- register epilogue (NPAD-padded outputs: no row guard) ----
    const int cb = wn * 32 + 2 * (lane & 3);
    const int rb = row0 + wm * 32 + (lane >> 2);

    if (mode == 0) {
        float2 bvv[4];
        #pragma unroll
        for (int j = 0; j < 4; j++) bvv[j] = *(const float2*)&bias[cb + j * 8];
        __half* out = (__half*)o0;
        #pragma unroll
        for (int i = 0; i < 2; i++) {
            size_t r1 = (size_t)(rb + i * 16) * 128;
            size_t r2 = r1 + 8 * 128;
            #pragma unroll
            for (int j = 0; j < 4; j++) {
                float* a = acc[i][j];
                int c = cb + j * 8;
                *(__half2*)&out[r1 + c] = __floats2half2_rn(fmaxf(a[0] + bvv[j].x, 0.f),
                                                            fmaxf(a[1] + bvv[j].y, 0.f));
                *(__half2*)&out[r2 + c] = __floats2half2_rn(fmaxf(a[2] + bvv[j].x, 0.f),
                                                            fmaxf(a[3] + bvv[j].y, 0.f));
            }
        }
    } else if (mode == 1) {
        __half* out = (__half*)o0;
        #pragma unroll
        for (int i = 0; i < 2; i++) {
            size_t r1 = (size_t)(rb + i * 16) * 128;
            size_t r2 = r1 + 8 * 128;
            #pragma unroll
            for (int j = 0; j < 4; j++) {
                float* a = acc[i][j];
                int c = cb + j * 8;
                *(__half2*)&out[r1 + c] = __floats2half2_rn(a[0], a[1]);
                *(__half2*)&out[r2 + c] = __floats2half2_rn(a[2], a[3]);
            }
        }
    } else if (mode == 2) {
        float* out = (float*)o0;
        #pragma unroll
        for (int i = 0; i < 2; i++) {
            size_t r1 = (size_t)(rb + i * 16) * 128;
            size_t r2 = r1 + 8 * 128;
            #pragma unroll
            for (int j = 0; j < 4; j++) {
                float* a = acc[i][j];
                int c = cb + j * 8;
                *(float2*)&out[r1 + c] = make_float2(a[0], a[1]);
                *(float2*)&out[r2 + c] = make_float2(a[2], a[3]);
            }
        }
    } else {   // mode 3: cols<64 -> fp16 o0 (ld64); cols>=64 -> f32 o1 (ld64)
        if (wn < 2) {
            __half* out = (__half*)o0;
            #pragma unroll
            for (int i = 0; i < 2; i++) {
                size_t r1 = (size_t)(rb + i * 16) * 64;
                size_t r2 = r1 + 8 * 64;
                #pragma unroll
                for (int j = 0; j < 4; j++) {
                    float* a = acc[i][j];
                    int c = cb + j * 8;
                    *(__half2*)&out[r1 + c] = __floats2half2_rn(a[0], a[1]);
                    *(__half2*)&out[r2 + c] = __floats2half2_rn(a[2], a[3]);
                }
            }
        } else {
            float* out = (float*)o1;
            #pragma unroll
            for (int i = 0; i < 2; i++) {
                size_t r1 = (size_t)(rb + i * 16) * 64;
                size_t r2 = r1 + 8 * 64;
                #pragma unroll
                for (int j = 0; j < 4; j++) {
                    float* a = acc[i][j];
                    int c = cb + j * 8 - 64;
                    *(float2*)&out[r1 + c] = make_float2(a[0], a[1]);
                    *(float2*)&out[r2 + c] = make_float2(a[2], a[3]);
                }
            }
        }
    }
}

// ======================= LayerNorm (fp16 in -> fp16 out) =======================
__global__ __launch_bounds__(256) void k_ln(const __half* __restrict__ in,
                                            __half* __restrict__ out,
                                            const float* __restrict__ g,
                                            const float* __restrict__ b)
{
    int R    = blockIdx.x * 8 + (threadIdx.x >> 5);
    int lane = threadIdx.x & 31;
    uint2 u = *(const uint2*)&in[(size_t)R * 128 + lane * 4];
    float2 f0 = __half22float2(*(__half2*)&u.x);
    float2 f1 = __half22float2(*(__half2*)&u.y);
    float v0 = f0.x, v1 = f0.y, v2 = f1.x, v3 = f1.y;
    float s = v0 + v1 + v2 + v3;
    #pragma unroll
    for (int o = 16; o; o >>= 1) s += __shfl_xor_sync(0xffffffffu, s, o);
    float mean = s * (1.f / 128.f);
    float d0 = v0 - mean, d1 = v1 - mean, d2 = v2 - mean, d3 = v3 - mean;
    float ss = d0 * d0 + d1 * d1 + d2 * d2 + d3 * d3;
    #pragma unroll
    for (int o = 16; o; o >>= 1) ss += __shfl_xor_sync(0xffffffffu, ss, o);
    float inv = 1.f / (sqrtf(ss * (1.f / 127.f)) + 1e-6f);
    float4 gg = *(const float4*)&g[lane * 4];
    float4 bb = *(const float4*)&b[lane * 4];
    __half2 o0 = __floats2half2_rn(gg.x * d0 * inv + bb.x, gg.y * d1 * inv + bb.y);
    __half2 o1 = __floats2half2_rn(gg.z * d2 * inv + bb.z, gg.w * d3 * inv + bb.w);
    *(uint2*)&out[(size_t)R * 128 + lane * 4] = make_uint2(*(unsigned*)&o0, *(unsigned*)&o1);
}

// ======================= GCN aggregate (fp16 gather) =======================
template <int OUT, int HOUT>
__global__ __launch_bounds__(256) void k_agg(const __half* __restrict__ supn,
                                             const float* __restrict__ selfm,
                                             const float* __restrict__ bias,
                                             void* __restrict__ out)
{
    const int V = OUT / 32;
    int node = blockIdx.x * 8 + (threadIdx.x >> 5);
    int lane = threadIdx.x & 31;

    float acc[V];
    {
        const float* sr = selfm + (size_t)node * OUT + lane * V;
        #pragma unroll
        for (int i = 0; i < V; i++) acc[i] = sr[i] + bias[lane * V + i];
    }

    int e0 = g_rowptr[node], e1 = g_rowptr[node + 1];
    for (int eb = e0; eb < e1; eb += 32) {
        int rem = e1 - eb;
        int c = 0; float wv = 0.f;
        if (lane < rem) { c = g_ecol[eb + lane]; wv = g_eval[eb + lane]; }
        if (rem >= 32) {
            #pragma unroll 8
            for (int j = 0; j < 32; j++) {
                int   cj = __shfl_sync(0xffffffffu, c, j);
                float wj = __shfl_sync(0xffffffffu, wv, j);
                const __half* srow = supn + (size_t)cj * OUT + lane * V;
                if (V == 4) {
                    uint2 u = *(const uint2*)srow;
                    float2 f0 = __half22float2(*(const __half2*)&u.x);
                    float2 f1 = __half22float2(*(const __half2*)&u.y);
                    acc[0] = fmaf(wj, f0.x, acc[0]);
                    acc[1] = fmaf(wj, f0.y, acc[1]);
                    acc[2] = fmaf(wj, f1.x, acc[2]);
                    acc[3] = fmaf(wj, f1.y, acc[3]);
                } else {
                    uint32_t u = *(const uint32_t*)srow;
                    float2 f0 = __half22float2(*(const __half2*)&u);
                    acc[0] = fmaf(wj, f0.x, acc[0]);
                    acc[1] = fmaf(wj, f0.y, acc[1]);
                }
            }
        } else {
            for (int j = 0; j < rem; j++) {
                int   cj = __shfl_sync(0xffffffffu, c, j);
                float wj = __shfl_sync(0xffffffffu, wv, j);
                const __half* srow = supn + (size_t)cj * OUT + lane * V;
                if (V == 4) {
                    uint2 u = *(const uint2*)srow;
                    float2 f0 = __half22float2(*(const __half2*)&u.x);
                    float2 f1 = __half22float2(*(const __half2*)&u.y);
                    acc[0] = fmaf(wj, f0.x, acc[0]);
                    acc[1] = fmaf(wj, f0.y, acc[1]);
                    acc[2] = fmaf(wj, f1.x, acc[2]);
                    acc[3] = fmaf(wj, f1.y, acc[3]);
                } else {
                    uint32_t u = *(const uint32_t*)srow;
                    float2 f0 = __half22float2(*(const __half2*)&u);
                    acc[0] = fmaf(wj, f0.x, acc[0]);
                    acc[1] = fmaf(wj, f0.y, acc[1]);
                }
            }
        }
    }

    if (HOUT) {
        __half* orow = (__half*)out + (size_t)node * OUT + lane * V;
        __half2 a = __floats2half2_rn(fmaxf(acc[0], 0.f), fmaxf(acc[1], 0.f));
        __half2 b = __floats2half2_rn(fmaxf(acc[2], 0.f), fmaxf(acc[3], 0.f));
        *(uint2*)orow = make_uint2(*(unsigned*)&a, *(unsigned*)&b);
    } else {
        float* orow = (float*)out + (size_t)node * OUT + lane * V;
        #pragma unroll
        for (int i = 0; i < V; i++) orow[i] = fmaxf(acc[i], 0.f);
    }
}

// ======================= launch =======================
extern "C" void kernel_launch(void* const* d_in, const int* in_sizes, int n_in,
                              void* d_out, int out_size)
{
    const float* x    = (const float*)d_in[0];
    const int*   er   = (const int*)d_in[1];
    const int*   ec   = (const int*)d_in[2];
    const float* ev   = (const float*)d_in[3];
    const float* fc1w = (const float*)d_in[4];
    const float* fc1b = (const float*)d_in[5];
    const float* fc2w = (const float*)d_in[6];
    const float* fc2b = (const float*)d_in[7];
    const float* lng  = (const float*)d_in[8];
    const float* lnb  = (const float*)d_in[9];
    const float *wn[4], *wsf[4], *gb[4];
    for (int i = 0; i < 4; i++) {
        wn[i]  = (const float*)d_in[10 + 3 * i];
        wsf[i] = (const float*)d_in[11 + 3 * i];
        gb[i]  = (const float*)d_in[12 + 3 * i];
    }
    float* outp = (float*)d_out;

    __half *s0, *s1, *supn, *wt;
    float* selfb;
    cudaGetSymbolAddress((void**)&s0,    g_h0);
    cudaGetSymbolAddress((void**)&s1,    g_h1);
    cudaGetSymbolAddress((void**)&supn,  g_supn);
    cudaGetSymbolAddress((void**)&selfb, g_self);
    cudaGetSymbolAddress((void**)&wt,    g_wt);
    auto WT = [&](int t) { return wt + (size_t)t * 16384; };

    cudaFuncSetAttribute(k_mm, cudaFuncAttributeMaxDynamicSharedMemorySize, MM_SMEM);

    const int MT = NPAD / TM;   // 1564

    k_wprep<<<dim3(128, 9), 128>>>(fc1w, fc2w, wn[0], wsf[0], wn[1], wsf[1],
                                   wn[2], wsf[2], wn[3], wsf[3], wt);            // 0
    k_xprep<<<NPAD / 8, 256>>>(x, s0);                                           // 1
    k_zero_rowptr<<<(NP1 + 255) / 256, 256>>>();                                 // 2
    k_mm<<<MT, 256, MM_SMEM>>>(s0, WT(0), fc1b, s1, nullptr, 0);                 // 3 <- profiled
    k_hist<<<(N_EDGES + 255) / 256, 256>>>(er);                                  // 4
    k_scan1<<<NSCAN_BLOCKS, 1024>>>();                                           // 5
    k_scan2<<<1, 1>>>();                                                         // 6
    k_scan3<<<NSCAN_BLOCKS, 1024>>>();                                           // 7
    k_fill<<<(N_EDGES + 255) / 256, 256>>>(er, ec, ev);                          // 8
    k_mm<<<MT, 256, MM_SMEM>>>(s1, WT(1), fc2b, s0, nullptr, 0);                 // 9
    k_ln<<<N_NODES / 8, 256>>>(s0, s1, lng, lnb);                                // 10

    __half* cur = s1;
    __half* nxt = s0;
    for (int l = 0; l < 3; l++) {
        k_mm<<<MT, 256, MM_SMEM>>>(cur, WT(2 + 2 * l), nullptr, supn, nullptr, 1);
        k_mm<<<MT, 256, MM_SMEM>>>(cur, WT(3 + 2 * l), nullptr, selfb, nullptr, 2);
        k_agg<128, 1><<<N_NODES / 8, 256>>>(supn, selfb, gb[l], nxt);
        __half* t = cur; cur = nxt; nxt = t;
    }

    k_mm<<<MT, 256, MM_SMEM>>>(cur, WT(8), nullptr, supn, selfb, 3);
    k_agg<64, 0><<<N_NODES / 8, 256>>>(supn, selfb, gb[3], outp);
}

// round 15
// speedup vs baseline: 1.3834x; 1.0185x over previous
#include <cuda_runtime.h>
#include <cuda_fp16.h>
#include <math.h>
#include <stdint.h>

#define N_NODES 100000
#define NPAD    100096
#define N_EDGES 3200000
#define NP1     100001
#define NSCAN_BLOCKS 98

#define LDA  136                       // A smem row stride (fp16): 128 + 8 pad
#define TM   64                        // rows per CTA tile
#define A_BYTES (TM * LDA * 2)         // 17408
#define WT_TILE_BYTES 32768            // packed fp16 B tile: 8 ks x 8 pair x 512B
#define MM_SMEM_MAX (A_BYTES + 2 * WT_TILE_BYTES)   // 82944

// ======================= device scratch =======================
__device__ int    g_rowptr[NP1];
__device__ int    g_bsum[128];
__device__ int    g_pos[N_NODES];
__device__ int    g_ecol[N_EDGES];
__device__ float  g_eval[N_EDGES];
__device__ __half g_h0[(size_t)NPAD * 128];
__device__ __half g_h1[(size_t)NPAD * 128];
__device__ __half g_supn[(size_t)NPAD * 128];
__device__ __half g_self[(size_t)NPAD * 128];
__device__ __half g_wt[9 * 16384];

// ======================= helpers =======================
__device__ __forceinline__ uint32_t smem_u32(const void* p) {
    uint32_t a;
    asm("{ .reg .u64 t; cvta.to.shared.u64 t, %1; cvt.u32.u64 %0, t; }" : "=r"(a) : "l"(p));
    return a;
}
__device__ __forceinline__ void ldsm_x4(unsigned* r, uint32_t addr) {
    asm volatile("ldmatrix.sync.aligned.m8n8.x4.shared.b16 {%0,%1,%2,%3}, [%4];"
        : "=r"(r[0]), "=r"(r[1]), "=r"(r[2]), "=r"(r[3]) : "r"(addr));
}
__device__ __forceinline__ uint4 lds128(uint32_t addr) {
    uint4 r;
    asm volatile("ld.shared.v4.b32 {%0,%1,%2,%3}, [%4];"
        : "=r"(r.x), "=r"(r.y), "=r"(r.z), "=r"(r.w) : "r"(addr));
    return r;
}
__device__ __forceinline__ void mma_fp16(float* c, const unsigned* a, unsigned b0, unsigned b1) {
    asm volatile("mma.sync.aligned.m16n8k16.row.col.f32.f16.f16.f32 "
        "{%0,%1,%2,%3}, {%4,%5,%6,%7}, {%8,%9}, {%0,%1,%2,%3};"
        : "+f"(c[0]), "+f"(c[1]), "+f"(c[2]), "+f"(c[3])
        : "r"(a[0]), "r"(a[1]), "r"(a[2]), "r"(a[3]), "r"(b0), "r"(b1));
}
__device__ __forceinline__ void cpasync16(uint32_t dst, const void* src) {
    asm volatile("cp.async.cg.shared.global [%0], [%1], 16;" :: "r"(dst), "l"(src));
}

// ======================= CSR build =======================
__global__ void k_zero_rowptr() {
    int i = blockIdx.x * blockDim.x + threadIdx.x;
    if (i < NP1) g_rowptr[i] = 0;
}
__global__ void k_hist(const int* __restrict__ rows) {
    int e = blockIdx.x * blockDim.x + threadIdx.x;
    if (e < N_EDGES) atomicAdd(&g_rowptr[rows[e] + 1], 1);
}
__global__ void k_scan1() {
    __shared__ int s[1024];
    int t = threadIdx.x, i = blockIdx.x * 1024 + t;
    int v = (i < NP1) ? g_rowptr[i] : 0;
    s[t] = v; __syncthreads();
    #pragma unroll
    for (int off = 1; off < 1024; off <<= 1) {
        int tv = 0;
        if (t >= off) tv = s[t - off];
        __syncthreads(); s[t] += tv; __syncthreads();
    }
    if (i < NP1) g_rowptr[i] = s[t];
    if (t == 1023) g_bsum[blockIdx.x] = s[1023];
}
__global__ void k_scan2() {
    int acc = 0;
    for (int b = 0; b < NSCAN_BLOCKS; b++) { acc += g_bsum[b]; g_bsum[b] = acc; }
}
__global__ void k_scan3() {
    int b = blockIdx.x;
    int i = b * 1024 + threadIdx.x;
    int add = b ? g_bsum[b - 1] : 0;
    if (i < NP1) {
        int v = g_rowptr[i] + add;
        g_rowptr[i] = v;
        if (i < N_NODES) g_pos[i] = v;
    }
}
__global__ void k_fill(const int* __restrict__ rows, const int* __restrict__ cols,
                       const float* __restrict__ vals) {
    int e = blockIdx.x * blockDim.x + threadIdx.x;
    if (e >= N_EDGES) return;
    int r = rows[e];
    int p = atomicAdd(&g_pos[r], 1);
    g_ecol[p] = cols[e];
    g_eval[p] = vals[e];
}

// ======================= weight prep: pack fp16 B, j-pair-contiguous ============
__global__ void k_wprep(const float* __restrict__ fc1w, const float* __restrict__ fc2w,
                        const float* __restrict__ w0n, const float* __restrict__ w0s,
                        const float* __restrict__ w1n, const float* __restrict__ w1s,
                        const float* __restrict__ w2n, const float* __restrict__ w2s,
                        const float* __restrict__ w3n, const float* __restrict__ w3s,
                        __half* __restrict__ wt)
{
    int t = blockIdx.y, n = blockIdx.x, k = threadIdx.x;
    float v;
    switch (t) {
        case 0: v = fc1w[n * 128 + k]; break;
        case 1: v = fc2w[n * 128 + k]; break;
        case 2: v = w0n[k * 128 + n]; break;
        case 3: v = w0s[k * 128 + n]; break;
        case 4: v = w1n[k * 128 + n]; break;
        case 5: v = w1s[k * 128 + n]; break;
        case 6: v = w2n[k * 128 + n]; break;
        case 7: v = w2s[k * 128 + n]; break;
        default: v = (n < 64) ? w3n[k * 64 + n] : w3s[k * 64 + (n - 64)]; break;
    }
    int ks = k >> 4, kk = k & 15;
    int q, e;
    if (kk < 8) { q = kk >> 1; e = kk & 1; }
    else        { q = (kk - 8) >> 1; e = 2 + (kk & 1); }
    int nb = n >> 3, n7 = n & 7;
    char* base = (char*)wt + (size_t)t * WT_TILE_BYTES
               + ((ks * 8 + (nb >> 1)) * 512) + n7 * 64 + q * 16 + (nb & 1) * 8;
    *(__half*)(base + e * 2) = __float2half_rn(v);
}

// ======================= X prep: f32 -> fp16 rows =======================
__global__ __launch_bounds__(256) void k_xprep(const float* __restrict__ X, __half* __restrict__ dst) {
    int R = blockIdx.x * 8 + (threadIdx.x >> 5);
    int lane = threadIdx.x & 31;
    float4 v = make_float4(0.f, 0.f, 0.f, 0.f);
    if (R < N_NODES) v = *(const float4*)&X[(size_t)R * 128 + lane * 4];
    __half2 a = __floats2half2_rn(v.x, v.y);
    __half2 b = __floats2half2_rn(v.z, v.w);
    *(uint2*)&dst[(size_t)R * 128 + lane * 4] = make_uint2(*(unsigned*)&a, *(unsigned*)&b);
}

// ======================= fp16 GEMM: all-smem, reg-double-buffered ===============
// modes: 0 = bias+relu -> fp16 (ld128) ; 1 = raw fp16 (ld128) ;
//        3 = split64: wn<2 -> fp16 o (ld64), wn>=2 -> fp16 o1 (ld64)
__global__ __launch_bounds__(256) void k_mm(
    const __half* __restrict__ Asp,
    const __half* __restrict__ Bw,
    const float* __restrict__ bias,
    void* __restrict__ o0, int m0,
    void* __restrict__ o1, int m1,
    int nH)
{
    extern __shared__ __half As[];   // A: TM x LDA ; B tiles at +A_BYTES

    const int tid = threadIdx.x, wid = tid >> 5, lane = tid & 31;
    const int wm = wid >> 2, wn = wid & 3;   // warp tile: 32 rows x 32 cols
    const int row0 = blockIdx.x * TM;
    const uint32_t sbase = smem_u32(As);

    // ---- prologue: cp.async A (16KB) + B tiles (nH * 32KB) ----
    {
        const char* gA = (const char*)(Asp + (size_t)row0 * 128);
        #pragma unroll
        for (int it = 0; it < 4; it++) {
            int i = tid + 256 * it;          // 1024 x 16B
            int r = i >> 4, c = i & 15;
            cpasync16(sbase + r * (LDA * 2) + c * 16, gA + (size_t)i * 16);
        }
        const char* gB = (const char*)Bw;
        int nB = nH * 2048;
        for (int i = tid; i < nB; i += 256)
            cpasync16(sbase + A_BYTES + i * 16, gB + (size_t)i * 16);
        asm volatile("cp.async.commit_group;" ::: "memory");
        asm volatile("cp.async.wait_group 0;" ::: "memory");
    }
    __syncthreads();

    const uint32_t aBase = sbase +
        2u * (uint32_t)((wm * 32 + (lane & 15)) * LDA + ((lane >> 4) << 3));

    for (int nh = 0; nh < nH; nh++) {
        const uint32_t bBase = sbase + A_BYTES + nh * WT_TILE_BYTES
                             + (wn * 2) * 512 + lane * 16;
        float acc[2][4][4];
        #pragma unroll
        for (int i = 0; i < 2; i++)
            #pragma unroll
            for (int j = 0; j < 4; j++)
                #pragma unroll
                for (int q = 0; q < 4; q++) acc[i][j][q] = 0.f;

        // prime ks=0
        uint4 u0 = lds128(bBase + 0);
        uint4 u1 = lds128(bBase + 512);
        unsigned ah[2][4];
        ldsm_x4(ah[0], aBase);
        ldsm_x4(ah[1], aBase + 2u * (16 * LDA));

        #pragma unroll
        for (int ks = 0; ks < 8; ks++) {
            uint4 nu0, nu1;
            unsigned nah[2][4];
            if (ks < 7) {
                const int kn = ks + 1;
                nu0 = lds128(bBase + kn * 4096);
                nu1 = lds128(bBase + kn * 4096 + 512);
                ldsm_x4(nah[0], aBase + 2u * (uint32_t)(kn * 16));
                ldsm_x4(nah[1], aBase + 2u * (uint32_t)(16 * LDA + kn * 16));
            }
            #pragma unroll
            for (int i = 0; i < 2; i++) {
                mma_fp16(acc[i][0], ah[i], u0.x, u0.y);
                mma_fp16(acc[i][1], ah[i], u0.z, u0.w);
                mma_fp16(acc[i][2], ah[i], u1.x, u1.y);
                mma_fp16(acc[i][3], ah[i], u1.z, u1.w);
            }
            if (ks < 7) {
                u0 = nu0; u1 = nu1;
                #pragma unroll
                for (int i = 0; i < 2; i++)
                    #pragma unroll
                    for (int q = 0; q < 4; q++) ah[i][q] = nah[i][q];
            }
        }

        // ---- register epilogue (NPAD-padded fp16 outputs: no row guard) ----
        const int mode = (nh == 0) ? m0 : m1;
        void* oh = (nh == 0) ? o0 : o1;
        const int cb = wn * 32 + 2 * (lane & 3);
        const int rb = row0 + wm * 32 + (lane >> 2);

        if (mode == 0) {
            float2 bvv[4];
            #pragma unroll
            for (int j = 0; j < 4; j++) bvv[j] = *(const float2*)&bias[cb + j * 8];
            __half* out = (__half*)oh;
            #pragma unroll
            for (int i = 0; i < 2; i++) {
                size_t r1 = (size_t)(rb + i * 16) * 128;
                size_t r2 = r1 + 8 * 128;
                #pragma unroll
                for (int j = 0; j < 4; j++) {
                    float* a = acc[i][j];
                    int c = cb + j * 8;
                    *(__half2*)&out[r1 + c] = __floats2half2_rn(fmaxf(a[0] + bvv[j].x, 0.f),
                                                                fmaxf(a[1] + bvv[j].y, 0.f));
                    *(__half2*)&out[r2 + c] = __floats2half2_rn(fmaxf(a[2] + bvv[j].x, 0.f),
                                                                fmaxf(a[3] + bvv[j].y, 0.f));
                }
            }
        } else if (mode == 1) {
            __half* out = (__half*)oh;
            #pragma unroll
            for (int i = 0; i < 2; i++) {
                size_t r1 = (size_t)(rb + i * 16) * 128;
                size_t r2 = r1 + 8 * 128;
                #pragma unroll
                for (int j = 0; j < 4; j++) {
                    float* a = acc[i][j];
                    int c = cb + j * 8;
                    *(__half2*)&out[r1 + c] = __floats2half2_rn(a[0], a[1]);
                    *(__half2*)&out[r2 + c] = __floats2half2_rn(a[2], a[3]);
                }
            }
        } else {   // mode 3: cols<64 -> o0 (supn); cols>=64 -> o1 (selfb), both fp16 ld64
            __half* out = (wn < 2) ? (__half*)o0 : (__half*)o1;
            int coff = (wn < 2) ? 0 : 64;
            #pragma unroll
            for (int i = 0; i < 2; i++) {
                size_t r1 = (size_t)(rb + i * 16) * 64;
                size_t r2 = r1 + 8 * 64;
                #pragma unroll
                for (int j = 0; j < 4; j++) {
                    float* a = acc[i][j];
                    int c = cb + j * 8 - coff;
                    *(__half2*)&out[r1 + c] = __floats2half2_rn(a[0], a[1]);
                    *(__half2*)&out[r2 + c] = __floats2half2_rn(a[2], a[3]);
                }
            }
        }
    }
}

// ======================= LayerNorm (fp16 in -> fp16 out) =======================
__global__ __launch_bounds__(256) void k_ln(const __half* __restrict__ in,
                                            __half* __restrict__ out,
                                            const float* __restrict__ g,
                                            const float* __restrict__ b)
{
    int R    = blockIdx.x * 8 + (threadIdx.x >> 5);
    int lane = threadIdx.x & 31;
    uint2 u = *(const uint2*)&in[(size_t)R * 128 + lane * 4];
    float2 f0 = __half22float2(*(__half2*)&u.x);
    float2 f1 = __half22float2(*(__half2*)&u.y);
    float v0 = f0.x, v1 = f0.y, v2 = f1.x, v3 = f1.y;
    float s = v0 + v1 + v2 + v3;
    #pragma unroll
    for (int o = 16; o; o >>= 1) s += __shfl_xor_sync(0xffffffffu, s, o);
    float mean = s * (1.f / 128.f);
    float d0 = v0 - mean, d1 = v1 - mean, d2 = v2 - mean, d3 = v3 - mean;
    float ss = d0 * d0 + d1 * d1 + d2 * d2 + d3 * d3;
    #pragma unroll
    for (int o = 16; o; o >>= 1) ss += __shfl_xor_sync(0xffffffffu, ss, o);
    float inv = 1.f / (sqrtf(ss * (1.f / 127.f)) + 1e-6f);
    float4 gg = *(const float4*)&g[lane * 4];
    float4 bb = *(const float4*)&b[lane * 4];
    __half2 o0 = __floats2half2_rn(gg.x * d0 * inv + bb.x, gg.y * d1 * inv + bb.y);
    __half2 o1 = __floats2half2_rn(gg.z * d2 * inv + bb.z, gg.w * d3 * inv + bb.w);
    *(uint2*)&out[(size_t)R * 128 + lane * 4] = make_uint2(*(unsigned*)&o0, *(unsigned*)&o1);
}

// ======================= GCN aggregate (fp16 gather, fp16 self) =================
template <int OUT, int HOUT>
__global__ __launch_bounds__(256) void k_agg(const __half* __restrict__ supn,
                                             const __half* __restrict__ selfm,
                                             const float* __restrict__ bias,
                                             void* __restrict__ out)
{
    const int V = OUT / 32;
    int node = blockIdx.x * 8 + (threadIdx.x >> 5);
    int lane = threadIdx.x & 31;

    float acc[V];
    {
        const __half* sr = selfm + (size_t)node * OUT + lane * V;
        if (V == 4) {
            uint2 u = *(const uint2*)sr;
            float2 f0 = __half22float2(*(const __half2*)&u.x);
            float2 f1 = __half22float2(*(const __half2*)&u.y);
            acc[0] = f0.x + bias[lane * 4 + 0];
            acc[1] = f0.y + bias[lane * 4 + 1];
            acc[2] = f1.x + bias[lane * 4 + 2];
            acc[3] = f1.y + bias[lane * 4 + 3];
        } else {
            uint32_t u = *(const uint32_t*)sr;
            float2 f0 = __half22float2(*(const __half2*)&u);
            acc[0] = f0.x + bias[lane * 2 + 0];
            acc[1] = f0.y + bias[lane * 2 + 1];
        }
    }

    int e0 = g_rowptr[node], e1 = g_rowptr[node + 1];
    for (int eb = e0; eb < e1; eb += 32) {
        int rem = e1 - eb;
        int c = 0; float wv = 0.f;
        if (lane < rem) { c = g_ecol[eb + lane]; wv = g_eval[eb + lane]; }
        if (rem >= 32) {
            #pragma unroll 8
            for (int j = 0; j < 32; j++) {
                int   cj = __shfl_sync(0xffffffffu, c, j);
                float wj = __shfl_sync(0xffffffffu, wv, j);
                const __half* srow = supn + (size_t)cj * OUT + lane * V;
                if (V == 4) {
                    uint2 u = *(const uint2*)srow;
                    float2 f0 = __half22float2(*(const __half2*)&u.x);
                    float2 f1 = __half22float2(*(const __half2*)&u.y);
                    acc[0] = fmaf(wj, f0.x, acc[0]);
                    acc[1] = fmaf(wj, f0.y, acc[1]);
                    acc[2] = fmaf(wj, f1.x, acc[2]);
                    acc[3] = fmaf(wj, f1.y, acc[3]);
                } else {
                    uint32_t u = *(const uint32_t*)srow;
                    float2 f0 = __half22float2(*(const __half2*)&u);
                    acc[0] = fmaf(wj, f0.x, acc[0]);
                    acc[1] = fmaf(wj, f0.y, acc[1]);
                }
            }
        } else {
            for (int j = 0; j < rem; j++) {
                int   cj = __shfl_sync(0xffffffffu, c, j);
                float wj = __shfl_sync(0xffffffffu, wv, j);
                const __half* srow = supn + (size_t)cj * OUT + lane * V;
                if (V == 4) {
                    uint2 u = *(const uint2*)srow;
                    float2 f0 = __half22float2(*(const __half2*)&u.x);
                    float2 f1 = __half22float2(*(const __half2*)&u.y);
                    acc[0] = fmaf(wj, f0.x, acc[0]);
                    acc[1] = fmaf(wj, f0.y, acc[1]);
                    acc[2] = fmaf(wj, f1.x, acc[2]);
                    acc[3] = fmaf(wj, f1.y, acc[3]);
                } else {
                    uint32_t u = *(const uint32_t*)srow;
                    float2 f0 = __half22float2(*(const __half2*)&u);
                    acc[0] = fmaf(wj, f0.x, acc[0]);
                    acc[1] = fmaf(wj, f0.y, acc[1]);
                }
            }
        }
    }

    if (HOUT) {
        __half* orow = (__half*)out + (size_t)node * OUT + lane * V;
        __half2 a = __floats2half2_rn(fmaxf(acc[0], 0.f), fmaxf(acc[1], 0.f));
        __half2 b = __floats2half2_rn(fmaxf(acc[2], 0.f), fmaxf(acc[3], 0.f));
        *(uint2*)orow = make_uint2(*(unsigned*)&a, *(unsigned*)&b);
    } else {
        float* orow = (float*)out + (size_t)node * OUT + lane * V;
        #pragma unroll
        for (int i = 0; i < V; i++) orow[i] = fmaxf(acc[i], 0.f);
    }
}

// ======================= launch =======================
extern "C" void kernel_launch(void* const* d_in, const int* in_sizes, int n_in,
                              void* d_out, int out_size)
{
    const float* x    = (const float*)d_in[0];
    const int*   er   = (const int*)d_in[1];
    const int*   ec   = (const int*)d_in[2];
    const float* ev   = (const float*)d_in[3];
    const float* fc1w = (const float*)d_in[4];
    const float* fc1b = (const float*)d_in[5];
    const float* fc2w = (const float*)d_in[6];
    const float* fc2b = (const float*)d_in[7];
    const float* lng  = (const float*)d_in[8];
    const float* lnb  = (const float*)d_in[9];
    const float *wn[4], *wsf[4], *gb[4];
    for (int i = 0; i < 4; i++) {
        wn[i]  = (const float*)d_in[10 + 3 * i];
        wsf[i] = (const float*)d_in[11 + 3 * i];
        gb[i]  = (const float*)d_in[12 + 3 * i];
    }
    float* outp = (float*)d_out;

    __half *s0, *s1, *supn, *selfb, *wt;
    cudaGetSymbolAddress((void**)&s0,    g_h0);
    cudaGetSymbolAddress((void**)&s1,    g_h1);
    cudaGetSymbolAddress((void**)&supn,  g_supn);
    cudaGetSymbolAddress((void**)&selfb, g_self);
    cudaGetSymbolAddress((void**)&wt,    g_wt);
    auto WT = [&](int t) { return wt + (size_t)t * 16384; };

    cudaFuncSetAttribute(k_mm, cudaFuncAttributeMaxDynamicSharedMemorySize, MM_SMEM_MAX);

    const int MT = NPAD / TM;   // 1564
    const int SM1 = A_BYTES + WT_TILE_BYTES;
    const int SM2 = A_BYTES + 2 * WT_TILE_BYTES;

    k_wprep<<<dim3(128, 9), 128>>>(fc1w, fc2w, wn[0], wsf[0], wn[1], wsf[1],
                                   wn[2], wsf[2], wn[3], wsf[3], wt);            // 0
    k_xprep<<<NPAD / 8, 256>>>(x, s0);                                           // 1
    k_zero_rowptr<<<(NP1 + 255) / 256, 256>>>();                                 // 2
    k_mm<<<MT, 256, SM1>>>(s0, WT(0), fc1b, s1, 0, nullptr, 0, 1);               // 3 <- profiled
    k_hist<<<(N_EDGES + 255) / 256, 256>>>(er);                                  // 4
    k_scan1<<<NSCAN_BLOCKS, 1024>>>();                                           // 5
    k_scan2<<<1, 1>>>();                                                         // 6
    k_scan3<<<NSCAN_BLOCKS, 1024>>>();                                           // 7
    k_fill<<<(N_EDGES + 255) / 256, 256>>>(er, ec, ev);                          // 8
    k_mm<<<MT, 256, SM1>>>(s1, WT(1), fc2b, s0, 0, nullptr, 0, 1);               // 9
    k_ln<<<N_NODES / 8, 256>>>(s0, s1, lng, lnb);                                // 10

    __half* cur = s1;
    __half* nxt = s0;
    for (int l = 0; l < 3; l++) {
        k_mm<<<MT, 256, SM2>>>(cur, WT(2 + 2 * l), nullptr, supn, 1, selfb, 1, 2);
        k_agg<128, 1><<<N_NODES / 8, 256>>>(supn, selfb, gb[l], nxt);
        __half* t = cur; cur = nxt; nxt = t;
    }

    k_mm<<<MT, 256, SM1>>>(cur, WT(8), nullptr, supn, 3, selfb, 3, 1);
    k_agg<64, 0><<<N_NODES / 8, 256>>>(supn, selfb, gb[3], outp);
}

// round 16
// speedup vs baseline: 1.4217x; 1.0277x over previous
#include <cuda_runtime.h>
#include <cuda_fp16.h>
#include <math.h>
#include <stdint.h>

#define N_NODES 100000
#define NPAD    100096
#define N_EDGES 3200000
#define NP1     100001
#define NSCAN_BLOCKS 98

#define LDA  136                       // A smem row stride (fp16): 128 + 8 pad
#define TM   64                        // rows per CTA tile
#define A_BYTES (TM * LDA * 2)         // 17408
#define WT_TILE_BYTES 32768            // packed fp16 B tile: 8 ks x 8 pair x 512B
#define SMEM_MAX (A_BYTES + 2 * WT_TILE_BYTES)   // 82944

// ======================= device scratch =======================
__device__ int    g_rowptr[NP1];
__device__ int    g_bsum[128];
__device__ int    g_pos[N_NODES];
__device__ int    g_ecol[N_EDGES];
__device__ float  g_eval[N_EDGES];
__device__ __half g_h0[(size_t)NPAD * 128];
__device__ __half g_h1[(size_t)NPAD * 128];
__device__ __half g_supn[(size_t)NPAD * 128];
__device__ __half g_self[(size_t)NPAD * 128];
__device__ __half g_wt[9 * 16384];

// ======================= helpers =======================
__device__ __forceinline__ uint32_t smem_u32(const void* p) {
    uint32_t a;
    asm("{ .reg .u64 t; cvta.to.shared.u64 t, %1; cvt.u32.u64 %0, t; }" : "=r"(a) : "l"(p));
    return a;
}
__device__ __forceinline__ void ldsm_x4(unsigned* r, uint32_t addr) {
    asm volatile("ldmatrix.sync.aligned.m8n8.x4.shared.b16 {%0,%1,%2,%3}, [%4];"
        : "=r"(r[0]), "=r"(r[1]), "=r"(r[2]), "=r"(r[3]) : "r"(addr));
}
__device__ __forceinline__ uint4 lds128(uint32_t addr) {
    uint4 r;
    asm volatile("ld.shared.v4.b32 {%0,%1,%2,%3}, [%4];"
        : "=r"(r.x), "=r"(r.y), "=r"(r.z), "=r"(r.w) : "r"(addr));
    return r;
}
__device__ __forceinline__ void mma_fp16(float* c, const unsigned* a, unsigned b0, unsigned b1) {
    asm volatile("mma.sync.aligned.m16n8k16.row.col.f32.f16.f16.f32 "
        "{%0,%1,%2,%3}, {%4,%5,%6,%7}, {%8,%9}, {%0,%1,%2,%3};"
        : "+f"(c[0]), "+f"(c[1]), "+f"(c[2]), "+f"(c[3])
        : "r"(a[0]), "r"(a[1]), "r"(a[2]), "r"(a[3]), "r"(b0), "r"(b1));
}
__device__ __forceinline__ void cpasync16(uint32_t dst, const void* src) {
    asm volatile("cp.async.cg.shared.global [%0], [%1], 16;" :: "r"(dst), "l"(src));
}

// ======================= CSR build =======================
__global__ void k_zero_rowptr() {
    int i = blockIdx.x * blockDim.x + threadIdx.x;
    if (i < NP1) g_rowptr[i] = 0;
}
__global__ void k_hist(const int* __restrict__ rows) {
    int e = blockIdx.x * blockDim.x + threadIdx.x;
    if (e < N_EDGES) atomicAdd(&g_rowptr[rows[e] + 1], 1);
}
__global__ void k_scan1() {
    __shared__ int s[1024];
    int t = threadIdx.x, i = blockIdx.x * 1024 + t;
    int v = (i < NP1) ? g_rowptr[i] : 0;
    s[t] = v; __syncthreads();
    #pragma unroll
    for (int off = 1; off < 1024; off <<= 1) {
        int tv = 0;
        if (t >= off) tv = s[t - off];
        __syncthreads(); s[t] += tv; __syncthreads();
    }
    if (i < NP1) g_rowptr[i] = s[t];
    if (t == 1023) g_bsum[blockIdx.x] = s[1023];
}
__global__ void k_scan2() {
    int acc = 0;
    for (int b = 0; b < NSCAN_BLOCKS; b++) { acc += g_bsum[b]; g_bsum[b] = acc; }
}
__global__ void k_scan3() {
    int b = blockIdx.x;
    int i = b * 1024 + threadIdx.x;
    int add = b ? g_bsum[b - 1] : 0;
    if (i < NP1) {
        int v = g_rowptr[i] + add;
        g_rowptr[i] = v;
        if (i < N_NODES) g_pos[i] = v;
    }
}
__global__ void k_fill(const int* __restrict__ rows, const int* __restrict__ cols,
                       const float* __restrict__ vals) {
    int e = blockIdx.x * blockDim.x + threadIdx.x;
    if (e >= N_EDGES) return;
    int r = rows[e];
    int p = atomicAdd(&g_pos[r], 1);
    g_ecol[p] = cols[e];
    g_eval[p] = vals[e];
}

// ======================= weight prep: pack fp16 B, j-pair-contiguous ============
__global__ void k_wprep(const float* __restrict__ fc1w, const float* __restrict__ fc2w,
                        const float* __restrict__ w0n, const float* __restrict__ w0s,
                        const float* __restrict__ w1n, const float* __restrict__ w1s,
                        const float* __restrict__ w2n, const float* __restrict__ w2s,
                        const float* __restrict__ w3n, const float* __restrict__ w3s,
                        __half* __restrict__ wt)
{
    int t = blockIdx.y, n = blockIdx.x, k = threadIdx.x;
    float v;
    switch (t) {
        case 0: v = fc1w[n * 128 + k]; break;
        case 1: v = fc2w[n * 128 + k]; break;
        case 2: v = w0n[k * 128 + n]; break;
        case 3: v = w0s[k * 128 + n]; break;
        case 4: v = w1n[k * 128 + n]; break;
        case 5: v = w1s[k * 128 + n]; break;
        case 6: v = w2n[k * 128 + n]; break;
        case 7: v = w2s[k * 128 + n]; break;
        default: v = (n < 64) ? w3n[k * 64 + n] : w3s[k * 64 + (n - 64)]; break;
    }
    int ks = k >> 4, kk = k & 15;
    int q, e;
    if (kk < 8) { q = kk >> 1; e = kk & 1; }
    else        { q = (kk - 8) >> 1; e = 2 + (kk & 1); }
    int nb = n >> 3, n7 = n & 7;
    char* base = (char*)wt + (size_t)t * WT_TILE_BYTES
               + ((ks * 8 + (nb >> 1)) * 512) + n7 * 64 + q * 16 + (nb & 1) * 8;
    *(__half*)(base + e * 2) = __float2half_rn(v);
}

// ======================= shared GEMM mainloop (smem A + smem B) =================
__device__ __forceinline__ void mm_loop(float acc[2][4][4], uint32_t aBase, uint32_t bBase) {
    #pragma unroll
    for (int i = 0; i < 2; i++)
        #pragma unroll
        for (int j = 0; j < 4; j++)
            #pragma unroll
            for (int q = 0; q < 4; q++) acc[i][j][q] = 0.f;
    #pragma unroll
    for (int ks = 0; ks < 8; ks++) {
        const int ka = ks * 16;
        uint4 u0 = lds128(bBase + ks * 4096);
        uint4 u1 = lds128(bBase + ks * 4096 + 512);
        unsigned ah[2][4];
        #pragma unroll
        for (int i = 0; i < 2; i++)
            ldsm_x4(ah[i], aBase + 2u * (uint32_t)(i * 16 * LDA + ka));
        #pragma unroll
        for (int i = 0; i < 2; i++) {
            mma_fp16(acc[i][0], ah[i], u0.x, u0.y);
            mma_fp16(acc[i][1], ah[i], u0.z, u0.w);
            mma_fp16(acc[i][2], ah[i], u1.x, u1.y);
            mma_fp16(acc[i][3], ah[i], u1.z, u1.w);
        }
    }
}

// ======================= fused head: fc1 + fc2 + LayerNorm ======================
__global__ __launch_bounds__(256) void k_head(
    const float* __restrict__ X,
    const __half* __restrict__ Wt,   // W1 | W2, 64KB
    const float* __restrict__ b1, const float* __restrict__ b2,
    const float* __restrict__ lng, const float* __restrict__ lnb,
    __half* __restrict__ out)
{
    extern __shared__ __half As[];   // A: TM x LDA ; W at +A_BYTES (2 tiles)

    const int tid = threadIdx.x, wid = tid >> 5, lane = tid & 31;
    const int wm = wid >> 2, wn = wid & 3;
    const int row0 = blockIdx.x * TM;
    const uint32_t sbase = smem_u32(As);

    // W1+W2 async copy (64KB)
    {
        const char* gW = (const char*)Wt;
        #pragma unroll
        for (int it = 0; it < 16; it++) {
            int i = tid + 256 * it;
            cpasync16(sbase + A_BYTES + i * 16, gW + (size_t)i * 16);
        }
        asm volatile("cp.async.commit_group;" ::: "memory");
    }
    // x fp32 -> fp16 into A smem
    #pragma unroll
    for (int it = 0; it < 8; it++) {
        int i = tid + 256 * it;          // 2048 float4
        int r = i >> 5, c4 = i & 31;
        float4 v = make_float4(0.f, 0.f, 0.f, 0.f);
        int row = row0 + r;
        if (row < N_NODES) v = *(const float4*)&X[(size_t)row * 128 + c4 * 4];
        __half2 a = __floats2half2_rn(v.x, v.y);
        __half2 b = __floats2half2_rn(v.z, v.w);
        *(uint2*)&As[r * LDA + c4 * 4] = make_uint2(*(unsigned*)&a, *(unsigned*)&b);
    }
    asm volatile("cp.async.wait_group 0;" ::: "memory");
    __syncthreads();

    const uint32_t aBase = sbase +
        2u * (uint32_t)((wm * 32 + (lane & 15)) * LDA + ((lane >> 4) << 3));
    const uint32_t bB1 = sbase + A_BYTES + (wn * 2) * 512 + lane * 16;
    const uint32_t bB2 = bB1 + WT_TILE_BYTES;
    const int cb = wn * 32 + 2 * (lane & 3);
    const int rl = wm * 32 + (lane >> 2);

    float acc[2][4][4];

    // ---- fc1 ----
    mm_loop(acc, aBase, bB1);
    __syncthreads();   // done reading x
    {
        float2 bvv[4];
        #pragma unroll
        for (int j = 0; j < 4; j++) bvv[j] = *(const float2*)&b1[cb + j * 8];
        #pragma unroll
        for (int i = 0; i < 2; i++) {
            int r1 = rl + i * 16, r2 = r1 + 8;
            #pragma unroll
            for (int j = 0; j < 4; j++) {
                float* a = acc[i][j];
                int c = cb + j * 8;
                __half2 h1 = __floats2half2_rn(fmaxf(a[0] + bvv[j].x, 0.f),
                                               fmaxf(a[1] + bvv[j].y, 0.f));
                __half2 h2 = __floats2half2_rn(fmaxf(a[2] + bvv[j].x, 0.f),
                                               fmaxf(a[3] + bvv[j].y, 0.f));
                *(__half2*)&As[r1 * LDA + c] = h1;
                *(__half2*)&As[r2 * LDA + c] = h2;
            }
        }
    }
    __syncthreads();

    // ---- fc2 ----
    mm_loop(acc, aBase, bB2);
    __syncthreads();
    {
        float2 bvv[4];
        #pragma unroll
        for (int j = 0; j < 4; j++) bvv[j] = *(const float2*)&b2[cb + j * 8];
        #pragma unroll
        for (int i = 0; i < 2; i++) {
            int r1 = rl + i * 16, r2 = r1 + 8;
            #pragma unroll
            for (int j = 0; j < 4; j++) {
                float* a = acc[i][j];
                int c = cb + j * 8;
                __half2 h1 = __floats2half2_rn(fmaxf(a[0] + bvv[j].x, 0.f),
                                               fmaxf(a[1] + bvv[j].y, 0.f));
                __half2 h2 = __floats2half2_rn(fmaxf(a[2] + bvv[j].x, 0.f),
                                               fmaxf(a[3] + bvv[j].y, 0.f));
                *(__half2*)&As[r1 * LDA + c] = h1;
                *(__half2*)&As[r2 * LDA + c] = h2;
            }
        }
    }
    __syncthreads();

    // ---- LayerNorm: warp wid handles rows wid*8 .. wid*8+7 ----
    float4 gg = *(const float4*)&lng[lane * 4];
    float4 bb = *(const float4*)&lnb[lane * 4];
    #pragma unroll
    for (int rr = 0; rr < 8; rr++) {
        int r = wid * 8 + rr;
        uint2 u = *(const uint2*)&As[r * LDA + lane * 4];
        float2 f0 = __half22float2(*(__half2*)&u.x);
        float2 f1 = __half22float2(*(__half2*)&u.y);
        float v0 = f0.x, v1 = f0.y, v2 = f1.x, v3 = f1.y;
        float s = v0 + v1 + v2 + v3;
        #pragma unroll
        for (int o = 16; o; o >>= 1) s += __shfl_xor_sync(0xffffffffu, s, o);
        float mean = s * (1.f / 128.f);
        float d0 = v0 - mean, d1 = v1 - mean, d2 = v2 - mean, d3 = v3 - mean;
        float ss = d0 * d0 + d1 * d1 + d2 * d2 + d3 * d3;
        #pragma unroll
        for (int o = 16; o; o >>= 1) ss += __shfl_xor_sync(0xffffffffu, ss, o);
        float inv = 1.f / (sqrtf(ss * (1.f / 127.f)) + 1e-6f);
        __half2 o0 = __floats2half2_rn(gg.x * d0 * inv + bb.x, gg.y * d1 * inv + bb.y);
        __half2 o1 = __floats2half2_rn(gg.z * d2 * inv + bb.z, gg.w * d3 * inv + bb.w);
        *(uint2*)&out[(size_t)(row0 + r) * 128 + lane * 4] =
            make_uint2(*(unsigned*)&o0, *(unsigned*)&o1);
    }
}

// ======================= fp16 GEMM: all-smem simple mainloop ====================
// mode 1: nh0 -> o0, nh1 -> o1 (raw fp16 ld128); mode 3: split64 fp16
__global__ __launch_bounds__(256, 4) void k_mm(
    const __half* __restrict__ Asp,
    const __half* __restrict__ Bw,
    void* __restrict__ o0, void* __restrict__ o1, int mode, int nH)
{
    extern __shared__ __half As[];

    const int tid = threadIdx.x, wid = tid >> 5, lane = tid & 31;
    const int wm = wid >> 2, wn = wid & 3;
    const int row0 = blockIdx.x * TM;
    const uint32_t sbase = smem_u32(As);

    {
        const char* gA = (const char*)(Asp + (size_t)row0 * 128);
        #pragma unroll
        for (int it = 0; it < 4; it++) {
            int i = tid + 256 * it;
            int r = i >> 4, c = i & 15;
            cpasync16(sbase + r * (LDA * 2) + c * 16, gA + (size_t)i * 16);
        }
        const char* gB = (const char*)Bw;
        int nB = nH * 2048;
        for (int i = tid; i < nB; i += 256)
            cpasync16(sbase + A_BYTES + i * 16, gB + (size_t)i * 16);
        asm volatile("cp.async.commit_group;" ::: "memory");
        asm volatile("cp.async.wait_group 0;" ::: "memory");
    }
    __syncthreads();

    const uint32_t aBase = sbase +
        2u * (uint32_t)((wm * 32 + (lane & 15)) * LDA + ((lane >> 4) << 3));
    const int cb = wn * 32 + 2 * (lane & 3);
    const int rb = row0 + wm * 32 + (lane >> 2);

    for (int nh = 0; nh < nH; nh++) {
        const uint32_t bBase = sbase + A_BYTES + nh * WT_TILE_BYTES
                             + (wn * 2) * 512 + lane * 16;
        float acc[2][4][4];
        mm_loop(acc, aBase, bBase);

        if (mode == 1) {
            __half* out = (nh == 0) ? (__half*)o0 : (__half*)o1;
            #pragma unroll
            for (int i = 0; i < 2; i++) {
                size_t r1 = (size_t)(rb + i * 16) * 128;
                size_t r2 = r1 + 8 * 128;
                #pragma unroll
                for (int j = 0; j < 4; j++) {
                    float* a = acc[i][j];
                    int c = cb + j * 8;
                    *(__half2*)&out[r1 + c] = __floats2half2_rn(a[0], a[1]);
                    *(__half2*)&out[r2 + c] = __floats2half2_rn(a[2], a[3]);
                }
            }
        } else {   // mode 3
            __half* out = (wn < 2) ? (__half*)o0 : (__half*)o1;
            int coff = (wn < 2) ? 0 : 64;
            #pragma unroll
            for (int i = 0; i < 2; i++) {
                size_t r1 = (size_t)(rb + i * 16) * 64;
                size_t r2 = r1 + 8 * 64;
                #pragma unroll
                for (int j = 0; j < 4; j++) {
                    float* a = acc[i][j];
                    int c = cb + j * 8 - coff;
                    *(__half2*)&out[r1 + c] = __floats2half2_rn(a[0], a[1]);
                    *(__half2*)&out[r2 + c] = __floats2half2_rn(a[2], a[3]);
                }
            }
        }
    }
}

// ======================= GCN aggregate (fp16 gather, fp16 self) =================
template <int OUT, int HOUT>
__global__ __launch_bounds__(256) void k_agg(const __half* __restrict__ supn,
                                             const __half* __restrict__ selfm,
                                             const float* __restrict__ bias,
                                             void* __restrict__ out)
{
    const int V = OUT / 32;
    int node = blockIdx.x * 8 + (threadIdx.x >> 5);
    int lane = threadIdx.x & 31;

    float acc[V];
    {
        const __half* sr = selfm + (size_t)node * OUT + lane * V;
        if (V == 4) {
            uint2 u = *(const uint2*)sr;
            float2 f0 = __half22float2(*(const __half2*)&u.x);
            float2 f1 = __half22float2(*(const __half2*)&u.y);
            acc[0] = f0.x + bias[lane * 4 + 0];
            acc[1] = f0.y + bias[lane * 4 + 1];
            acc[2] = f1.x + bias[lane * 4 + 2];
            acc[3] = f1.y + bias[lane * 4 + 3];
        } else {
            uint32_t u = *(const uint32_t*)sr;
            float2 f0 = __half22float2(*(const __half2*)&u);
            acc[0] = f0.x + bias[lane * 2 + 0];
            acc[1] = f0.y + bias[lane * 2 + 1];
        }
    }

    int e0 = g_rowptr[node], e1 = g_rowptr[node + 1];
    for (int eb = e0; eb < e1; eb += 32) {
        int rem = e1 - eb;
        int c = 0; float wv = 0.f;
        if (lane < rem) { c = g_ecol[eb + lane]; wv = g_eval[eb + lane]; }
        if (rem >= 32) {
            #pragma unroll 8
            for (int j = 0; j < 32; j++) {
                int   cj = __shfl_sync(0xffffffffu, c, j);
                float wj = __shfl_sync(0xffffffffu, wv, j);
                const __half* srow = supn + (size_t)cj * OUT + lane * V;
                if (V == 4) {
                    uint2 u = *(const uint2*)srow;
                    float2 f0 = __half22float2(*(const __half2*)&u.x);
                    float2 f1 = __half22float2(*(const __half2*)&u.y);
                    acc[0] = fmaf(wj, f0.x, acc[0]);
                    acc[1] = fmaf(wj, f0.y, acc[1]);
                    acc[2] = fmaf(wj, f1.x, acc[2]);
                    acc[3] = fmaf(wj, f1.y, acc[3]);
                } else {
                    uint32_t u = *(const uint32_t*)srow;
                    float2 f0 = __half22float2(*(const __half2*)&u);
                    acc[0] = fmaf(wj, f0.x, acc[0]);
                    acc[1] = fmaf(wj, f0.y, acc[1]);
                }
            }
        } else {
            for (int j = 0; j < rem; j++) {
                int   cj = __shfl_sync(0xffffffffu, c, j);
                float wj = __shfl_sync(0xffffffffu, wv, j);
                const __half* srow = supn + (size_t)cj * OUT + lane * V;
                if (V == 4) {
                    uint2 u = *(const uint2*)srow;
                    float2 f0 = __half22float2(*(const __half2*)&u.x);
                    float2 f1 = __half22float2(*(const __half2*)&u.y);
                    acc[0] = fmaf(wj, f0.x, acc[0]);
                    acc[1] = fmaf(wj, f0.y, acc[1]);
                    acc[2] = fmaf(wj, f1.x, acc[2]);
                    acc[3] = fmaf(wj, f1.y, acc[3]);
                } else {
                    uint32_t u = *(const uint32_t*)srow;
                    float2 f0 = __half22float2(*(const __half2*)&u);
                    acc[0] = fmaf(wj, f0.x, acc[0]);
                    acc[1] = fmaf(wj, f0.y, acc[1]);
                }
            }
        }
    }

    if (HOUT) {
        __half* orow = (__half*)out + (size_t)node * OUT + lane * V;
        __half2 a = __floats2half2_rn(fmaxf(acc[0], 0.f), fmaxf(acc[1], 0.f));
        __half2 b = __floats2half2_rn(fmaxf(acc[2], 0.f), fmaxf(acc[3], 0.f));
        *(uint2*)orow = make_uint2(*(unsigned*)&a, *(unsigned*)&b);
    } else {
        float* orow = (float*)out + (size_t)node * OUT + lane * V;
        #pragma unroll
        for (int i = 0; i < V; i++) orow[i] = fmaxf(acc[i], 0.f);
    }
}

// ======================= launch =======================
extern "C" void kernel_launch(void* const* d_in, const int* in_sizes, int n_in,
                              void* d_out, int out_size)
{
    const float* x    = (const float*)d_in[0];
    const int*   er   = (const int*)d_in[1];
    const int*   ec   = (const int*)d_in[2];
    const float* ev   = (const float*)d_in[3];
    const float* fc1w = (const float*)d_in[4];
    const float* fc1b = (const float*)d_in[5];
    const float* fc2w = (const float*)d_in[6];
    const float* fc2b = (const float*)d_in[7];
    const float* lng  = (const float*)d_in[8];
    const float* lnb  = (const float*)d_in[9];
    const float *wn[4], *wsf[4], *gb[4];
    for (int i = 0; i < 4; i++) {
        wn[i]  = (const float*)d_in[10 + 3 * i];
        wsf[i] = (const float*)d_in[11 + 3 * i];
        gb[i]  = (const float*)d_in[12 + 3 * i];
    }
    float* outp = (float*)d_out;

    __half *s0, *s1, *supn, *selfb, *wt;
    cudaGetSymbolAddress((void**)&s0,    g_h0);
    cudaGetSymbolAddress((void**)&s1,    g_h1);
    cudaGetSymbolAddress((void**)&supn,  g_supn);
    cudaGetSymbolAddress((void**)&selfb, g_self);
    cudaGetSymbolAddress((void**)&wt,    g_wt);
    auto WT = [&](int t) { return wt + (size_t)t * 16384; };

    cudaFuncSetAttribute(k_head, cudaFuncAttributeMaxDynamicSharedMemorySize, SMEM_MAX);
    cudaFuncSetAttribute(k_mm,   cudaFuncAttributeMaxDynamicSharedMemorySize, SMEM_MAX);

    const int MT = NPAD / TM;   // 1564
    const int SM1 = A_BYTES + WT_TILE_BYTES;
    const int SM2 = A_BYTES + 2 * WT_TILE_BYTES;

    k_wprep<<<dim3(128, 9), 128>>>(fc1w, fc2w, wn[0], wsf[0], wn[1], wsf[1],
                                   wn[2], wsf[2], wn[3], wsf[3], wt);            // 0
    k_zero_rowptr<<<(NP1 + 255) / 256, 256>>>();                                 // 1
    k_hist<<<(N_EDGES + 255) / 256, 256>>>(er);                                  // 2
    k_head<<<MT, 256, SM2>>>(x, WT(0), fc1b, fc2b, lng, lnb, s0);                // 3 <- profiled
    k_scan1<<<NSCAN_BLOCKS, 1024>>>();                                           // 4
    k_scan2<<<1, 1>>>();                                                         // 5
    k_scan3<<<NSCAN_BLOCKS, 1024>>>();                                           // 6
    k_fill<<<(N_EDGES + 255) / 256, 256>>>(er, ec, ev);                          // 7

    __half* cur = s0;
    __half* nxt = s1;
    for (int l = 0; l < 3; l++) {
        k_mm<<<MT, 256, SM2>>>(cur, WT(2 + 2 * l), supn, selfb, 1, 2);
        k_agg<128, 1><<<N_NODES / 8, 256>>>(supn, selfb, gb[l], nxt);
        __half* t = cur; cur = nxt; nxt = t;
    }

    k_mm<<<MT, 256, SM1>>>(cur, WT(8), supn, selfb, 3, 1);
    k_agg<64, 0><<<N_NODES / 8, 256>>>(supn, selfb, gb[3], outp);
}

// round 17
// speedup vs baseline: 1.5411x; 1.0840x over previous
#include <cuda_runtime.h>
#include <cuda_fp16.h>
#include <math.h>
#include <stdint.h>

#define N_NODES 100000
#define NPAD    100096
#define N_EDGES 3200000
#define NP1     100001
#define NSCAN_BLOCKS 98

#define LDA  136
#define TM   64
#define A_BYTES (TM * LDA * 2)         // 17408
#define WT_TILE_BYTES 32768
#define MM_SMEM (A_BYTES + WT_TILE_BYTES)   // 50176

// ======================= device scratch =======================
__device__ int    g_rowptr[NP1];
__device__ int    g_bsum[128];
__device__ int    g_pos[N_NODES];
__device__ int2   g_edge[N_EDGES];            // {col, val_bits}
__device__ __half g_h0[(size_t)NPAD * 128];
__device__ __half g_h1[(size_t)NPAD * 128];
__device__ __half g_supn[(size_t)NPAD * 128];
__device__ __half g_self[(size_t)NPAD * 128];
__device__ __half g_wt[9 * 16384];

// ======================= helpers =======================
__device__ __forceinline__ uint32_t smem_u32(const void* p) {
    uint32_t a;
    asm("{ .reg .u64 t; cvta.to.shared.u64 t, %1; cvt.u32.u64 %0, t; }" : "=r"(a) : "l"(p));
    return a;
}
__device__ __forceinline__ void ldsm_x4(unsigned* r, uint32_t addr) {
    asm volatile("ldmatrix.sync.aligned.m8n8.x4.shared.b16 {%0,%1,%2,%3}, [%4];"
        : "=r"(r[0]), "=r"(r[1]), "=r"(r[2]), "=r"(r[3]) : "r"(addr));
}
__device__ __forceinline__ uint4 lds128(uint32_t addr) {
    uint4 r;
    asm volatile("ld.shared.v4.b32 {%0,%1,%2,%3}, [%4];"
        : "=r"(r.x), "=r"(r.y), "=r"(r.z), "=r"(r.w) : "r"(addr));
    return r;
}
__device__ __forceinline__ void mma_fp16(float* c, const unsigned* a, unsigned b0, unsigned b1) {
    asm volatile("mma.sync.aligned.m16n8k16.row.col.f32.f16.f16.f32 "
        "{%0,%1,%2,%3}, {%4,%5,%6,%7}, {%8,%9}, {%0,%1,%2,%3};"
        : "+f"(c[0]), "+f"(c[1]), "+f"(c[2]), "+f"(c[3])
        : "r"(a[0]), "r"(a[1]), "r"(a[2]), "r"(a[3]), "r"(b0), "r"(b1));
}
__device__ __forceinline__ void cpasync16(uint32_t dst, const void* src) {
    asm volatile("cp.async.cg.shared.global [%0], [%1], 16;" :: "r"(dst), "l"(src));
}

// ======================= CSR build =======================
__global__ void k_zero_rowptr() {
    int i = blockIdx.x * blockDim.x + threadIdx.x;
    if (i < NP1) g_rowptr[i] = 0;
}
__global__ void k_hist(const int* __restrict__ rows) {
    int e = blockIdx.x * blockDim.x + threadIdx.x;
    if (e < N_EDGES) atomicAdd(&g_rowptr[rows[e] + 1], 1);
}
__global__ void k_scan1() {
    __shared__ int s[1024];
    int t = threadIdx.x, i = blockIdx.x * 1024 + t;
    int v = (i < NP1) ? g_rowptr[i] : 0;
    s[t] = v; __syncthreads();
    #pragma unroll
    for (int off = 1; off < 1024; off <<= 1) {
        int tv = 0;
        if (t >= off) tv = s[t - off];
        __syncthreads(); s[t] += tv; __syncthreads();
    }
    if (i < NP1) g_rowptr[i] = s[t];
    if (t == 1023) g_bsum[blockIdx.x] = s[1023];
}
__global__ void k_scan2() {
    int acc = 0;
    for (int b = 0; b < NSCAN_BLOCKS; b++) { acc += g_bsum[b]; g_bsum[b] = acc; }
}
__global__ void k_scan3() {
    int b = blockIdx.x;
    int i = b * 1024 + threadIdx.x;
    int add = b ? g_bsum[b - 1] : 0;
    if (i < NP1) {
        int v = g_rowptr[i] + add;
        g_rowptr[i] = v;
        if (i < N_NODES) g_pos[i] = v;
    }
}
__global__ void k_fill(const int* __restrict__ rows, const int* __restrict__ cols,
                       const float* __restrict__ vals) {
    int e = blockIdx.x * blockDim.x + threadIdx.x;
    if (e >= N_EDGES) return;
    int r = rows[e];
    int p = atomicAdd(&g_pos[r], 1);
    g_edge[p] = make_int2(cols[e], __float_as_int(vals[e]));
}

// ======================= weight prep =======================
__global__ void k_wprep(const float* __restrict__ fc1w, const float* __restrict__ fc2w,
                        const float* __restrict__ w0n, const float* __restrict__ w0s,
                        const float* __restrict__ w1n, const float* __restrict__ w1s,
                        const float* __restrict__ w2n, const float* __restrict__ w2s,
                        const float* __restrict__ w3n, const float* __restrict__ w3s,
                        __half* __restrict__ wt)
{
    int t = blockIdx.y, n = blockIdx.x, k = threadIdx.x;
    float v;
    switch (t) {
        case 0: v = fc1w[n * 128 + k]; break;
        case 1: v = fc2w[n * 128 + k]; break;
        case 2: v = w0n[k * 128 + n]; break;
        case 3: v = w0s[k * 128 + n]; break;
        case 4: v = w1n[k * 128 + n]; break;
        case 5: v = w1s[k * 128 + n]; break;
        case 6: v = w2n[k * 128 + n]; break;
        case 7: v = w2s[k * 128 + n]; break;
        default: v = (n < 64) ? w3n[k * 64 + n] : w3s[k * 64 + (n - 64)]; break;
    }
    int ks = k >> 4, kk = k & 15;
    int q, e;
    if (kk < 8) { q = kk >> 1; e = kk & 1; }
    else        { q = (kk - 8) >> 1; e = 2 + (kk & 1); }
    int nb = n >> 3, n7 = n & 7;
    char* base = (char*)wt + (size_t)t * WT_TILE_BYTES
               + ((ks * 8 + (nb >> 1)) * 512) + n7 * 64 + q * 16 + (nb & 1) * 8;
    *(__half*)(base + e * 2) = __float2half_rn(v);
}

// ======================= shared GEMM mainloop =======================
__device__ __forceinline__ void mm_loop(float acc[2][4][4], uint32_t aBase, uint32_t bBase) {
    #pragma unroll
    for (int i = 0; i < 2; i++)
        #pragma unroll
        for (int j = 0; j < 4; j++)
            #pragma unroll
            for (int q = 0; q < 4; q++) acc[i][j][q] = 0.f;
    #pragma unroll
    for (int ks = 0; ks < 8; ks++) {
        const int ka = ks * 16;
        uint4 u0 = lds128(bBase + ks * 4096);
        uint4 u1 = lds128(bBase + ks * 4096 + 512);
        unsigned ah[2][4];
        #pragma unroll
        for (int i = 0; i < 2; i++)
            ldsm_x4(ah[i], aBase + 2u * (uint32_t)(i * 16 * LDA + ka));
        #pragma unroll
        for (int i = 0; i < 2; i++) {
            mma_fp16(acc[i][0], ah[i], u0.x, u0.y);
            mma_fp16(acc[i][1], ah[i], u0.z, u0.w);
            mma_fp16(acc[i][2], ah[i], u1.x, u1.y);
            mma_fp16(acc[i][3], ah[i], u1.z, u1.w);
        }
    }
}

// ======================= fused head: fc1 + fc2 + LN (50KB smem, 4 CTA/SM) =======
__global__ __launch_bounds__(256, 4) void k_head(
    const float* __restrict__ X,
    const __half* __restrict__ Wt,
    const float* __restrict__ b1, const float* __restrict__ b2,
    const float* __restrict__ lng, const float* __restrict__ lnb,
    __half* __restrict__ out)
{
    extern __shared__ __half As[];   // A: TM x LDA ; W buffer at +A_BYTES (32KB)

    const int tid = threadIdx.x, wid = tid >> 5, lane = tid & 31;
    const int wm = wid >> 2, wn = wid & 3;
    const int row0 = blockIdx.x * TM;
    const uint32_t sbase = smem_u32(As);

    // W1 async copy (32KB)
    {
        const char* gW = (const char*)Wt;
        #pragma unroll
        for (int it = 0; it < 8; it++) {
            int i = tid + 256 * it;
            cpasync16(sbase + A_BYTES + i * 16, gW + (size_t)i * 16);
        }
        asm volatile("cp.async.commit_group;" ::: "memory");
    }
    // x fp32 -> fp16 into A smem
    #pragma unroll
    for (int it = 0; it < 8; it++) {
        int i = tid + 256 * it;
        int r = i >> 5, c4 = i & 31;
        float4 v = make_float4(0.f, 0.f, 0.f, 0.f);
        int row = row0 + r;
        if (row < N_NODES) v = *(const float4*)&X[(size_t)row * 128 + c4 * 4];
        __half2 a = __floats2half2_rn(v.x, v.y);
        __half2 b = __floats2half2_rn(v.z, v.w);
        *(uint2*)&As[r * LDA + c4 * 4] = make_uint2(*(unsigned*)&a, *(unsigned*)&b);
    }
    asm volatile("cp.async.wait_group 0;" ::: "memory");
    __syncthreads();

    const uint32_t aBase = sbase +
        2u * (uint32_t)((wm * 32 + (lane & 15)) * LDA + ((lane >> 4) << 3));
    const uint32_t bB = sbase + A_BYTES + (wn * 2) * 512 + lane * 16;
    const int cb = wn * 32 + 2 * (lane & 3);
    const int rl = wm * 32 + (lane >> 2);

    float acc[2][4][4];

    // ---- fc1 ----
    mm_loop(acc, aBase, bB);
    __syncthreads();   // all warps done reading x and W1
    // issue W2 copy (overlaps h1 epilogue)
    {
        const char* gW = (const char*)Wt + WT_TILE_BYTES;
        #pragma unroll
        for (int it = 0; it < 8; it++) {
            int i = tid + 256 * it;
            cpasync16(sbase + A_BYTES + i * 16, gW + (size_t)i * 16);
        }
        asm volatile("cp.async.commit_group;" ::: "memory");
    }
    {
        float2 bvv[4];
        #pragma unroll
        for (int j = 0; j < 4; j++) bvv[j] = *(const float2*)&b1[cb + j * 8];
        #pragma unroll
        for (int i = 0; i < 2; i++) {
            int r1 = rl + i * 16, r2 = r1 + 8;
            #pragma unroll
            for (int j = 0; j < 4; j++) {
                float* a = acc[i][j];
                int c = cb + j * 8;
                *(__half2*)&As[r1 * LDA + c] =
                    __floats2half2_rn(fmaxf(a[0] + bvv[j].x, 0.f), fmaxf(a[1] + bvv[j].y, 0.f));
                *(__half2*)&As[r2 * LDA + c] =
                    __floats2half2_rn(fmaxf(a[2] + bvv[j].x, 0.f), fmaxf(a[3] + bvv[j].y, 0.f));
            }
        }
    }
    asm volatile("cp.async.wait_group 0;" ::: "memory");
    __syncthreads();

    // ---- fc2 ----
    mm_loop(acc, aBase, bB);
    __syncthreads();
    {
        float2 bvv[4];
        #pragma unroll
        for (int j = 0; j < 4; j++) bvv[j] = *(const float2*)&b2[cb + j * 8];
        #pragma unroll
        for (int i = 0; i < 2; i++) {
            int r1 = rl + i * 16, r2 = r1 + 8;
            #pragma unroll
            for (int j = 0; j < 4; j++) {
                float* a = acc[i][j];
                int c = cb + j * 8;
                *(__half2*)&As[r1 * LDA + c] =
                    __floats2half2_rn(fmaxf(a[0] + bvv[j].x, 0.f), fmaxf(a[1] + bvv[j].y, 0.f));
                *(__half2*)&As[r2 * LDA + c] =
                    __floats2half2_rn(fmaxf(a[2] + bvv[j].x, 0.f), fmaxf(a[3] + bvv[j].y, 0.f));
            }
        }
    }
    __syncthreads();

    // ---- LayerNorm: warp wid -> rows wid*8 .. +7 ----
    float4 gg = *(const float4*)&lng[lane * 4];
    float4 bb = *(const float4*)&lnb[lane * 4];
    #pragma unroll
    for (int rr = 0; rr < 8; rr++) {
        int r = wid * 8 + rr;
        uint2 u = *(const uint2*)&As[r * LDA + lane * 4];
        float2 f0 = __half22float2(*(__half2*)&u.x);
        float2 f1 = __half22float2(*(__half2*)&u.y);
        float v0 = f0.x, v1 = f0.y, v2 = f1.x, v3 = f1.y;
        float s = v0 + v1 + v2 + v3;
        #pragma unroll
        for (int o = 16; o; o >>= 1) s += __shfl_xor_sync(0xffffffffu, s, o);
        float mean = s * (1.f / 128.f);
        float d0 = v0 - mean, d1 = v1 - mean, d2 = v2 - mean, d3 = v3 - mean;
        float ss = d0 * d0 + d1 * d1 + d2 * d2 + d3 * d3;
        #pragma unroll
        for (int o = 16; o; o >>= 1) ss += __shfl_xor_sync(0xffffffffu, ss, o);
        float inv = 1.f / (sqrtf(ss * (1.f / 127.f)) + 1e-6f);
        __half2 o0 = __floats2half2_rn(gg.x * d0 * inv + bb.x, gg.y * d1 * inv + bb.y);
        __half2 o1 = __floats2half2_rn(gg.z * d2 * inv + bb.z, gg.w * d3 * inv + bb.w);
        *(uint2*)&out[(size_t)(row0 + r) * 128 + lane * 4] =
            make_uint2(*(unsigned*)&o0, *(unsigned*)&o1);
    }
}

// ======================= fp16 GEMM: sequential B staging (50KB, 4 CTA/SM) =======
// mode 1: nh0 -> o0, nh1 -> o1 (fp16 ld128); mode 3: split64 fp16
__global__ __launch_bounds__(256, 4) void k_mm(
    const __half* __restrict__ Asp,
    const __half* __restrict__ Bw,
    void* __restrict__ o0, void* __restrict__ o1, int mode, int nH)
{
    extern __shared__ __half As[];

    const int tid = threadIdx.x, wid = tid >> 5, lane = tid & 31;
    const int wm = wid >> 2, wn = wid & 3;
    const int row0 = blockIdx.x * TM;
    const uint32_t sbase = smem_u32(As);

    {
        const char* gA = (const char*)(Asp + (size_t)row0 * 128);
        #pragma unroll
        for (int it = 0; it < 4; it++) {
            int i = tid + 256 * it;
            int r = i >> 4, c = i & 15;
            cpasync16(sbase + r * (LDA * 2) + c * 16, gA + (size_t)i * 16);
        }
        const char* gB = (const char*)Bw;
        #pragma unroll
        for (int it = 0; it < 8; it++) {
            int i = tid + 256 * it;
            cpasync16(sbase + A_BYTES + i * 16, gB + (size_t)i * 16);
        }
        asm volatile("cp.async.commit_group;" ::: "memory");
        asm volatile("cp.async.wait_group 0;" ::: "memory");
    }
    __syncthreads();

    const uint32_t aBase = sbase +
        2u * (uint32_t)((wm * 32 + (lane & 15)) * LDA + ((lane >> 4) << 3));
    const uint32_t bBase = sbase + A_BYTES + (wn * 2) * 512 + lane * 16;
    const int cb = wn * 32 + 2 * (lane & 3);
    const int rb = row0 + wm * 32 + (lane >> 2);

    for (int nh = 0; nh < nH; nh++) {
        float acc[2][4][4];
        mm_loop(acc, aBase, bBase);

        if (nh + 1 < nH) {
            __syncthreads();   // all warps done with B(nh)
            const char* gB = (const char*)Bw + (size_t)(nh + 1) * WT_TILE_BYTES;
            #pragma unroll
            for (int it = 0; it < 8; it++) {
                int i = tid + 256 * it;
                cpasync16(sbase + A_BYTES + i * 16, gB + (size_t)i * 16);
            }
            asm volatile("cp.async.commit_group;" ::: "memory");
        }

        // epilogue (overlaps the B(nh+1) copy)
        if (mode == 1) {
            __half* out = (nh == 0) ? (__half*)o0 : (__half*)o1;
            #pragma unroll
            for (int i = 0; i < 2; i++) {
                size_t r1 = (size_t)(rb + i * 16) * 128;
                size_t r2 = r1 + 8 * 128;
                #pragma unroll
                for (int j = 0; j < 4; j++) {
                    float* a = acc[i][j];
                    int c = cb + j * 8;
                    *(__half2*)&out[r1 + c] = __floats2half2_rn(a[0], a[1]);
                    *(__half2*)&out[r2 + c] = __floats2half2_rn(a[2], a[3]);
                }
            }
        } else {   // mode 3
            __half* out = (wn < 2) ? (__half*)o0 : (__half*)o1;
            int coff = (wn < 2) ? 0 : 64;
            #pragma unroll
            for (int i = 0; i < 2; i++) {
                size_t r1 = (size_t)(rb + i * 16) * 64;
                size_t r2 = r1 + 8 * 64;
                #pragma unroll
                for (int j = 0; j < 4; j++) {
                    float* a = acc[i][j];
                    int c = cb + j * 8 - coff;
                    *(__half2*)&out[r1 + c] = __floats2half2_rn(a[0], a[1]);
                    *(__half2*)&out[r2 + c] = __floats2half2_rn(a[2], a[3]);
                }
            }
        }

        if (nh + 1 < nH) {
            asm volatile("cp.async.wait_group 0;" ::: "memory");
            __syncthreads();
        }
    }
}

// ======================= GCN aggregate (packed edges) =======================
template <int OUT, int HOUT>
__global__ __launch_bounds__(256) void k_agg(const __half* __restrict__ supn,
                                             const __half* __restrict__ selfm,
                                             const float* __restrict__ bias,
                                             void* __restrict__ out)
{
    const int V = OUT / 32;
    int node = blockIdx.x * 8 + (threadIdx.x >> 5);
    int lane = threadIdx.x & 31;

    float acc[V];
    {
        const __half* sr = selfm + (size_t)node * OUT + lane * V;
        if (V == 4) {
            uint2 u = *(const uint2*)sr;
            float2 f0 = __half22float2(*(const __half2*)&u.x);
            float2 f1 = __half22float2(*(const __half2*)&u.y);
            acc[0] = f0.x + bias[lane * 4 + 0];
            acc[1] = f0.y + bias[lane * 4 + 1];
            acc[2] = f1.x + bias[lane * 4 + 2];
            acc[3] = f1.y + bias[lane * 4 + 3];
        } else {
            uint32_t u = *(const uint32_t*)sr;
            float2 f0 = __half22float2(*(const __half2*)&u);
            acc[0] = f0.x + bias[lane * 2 + 0];
            acc[1] = f0.y + bias[lane * 2 + 1];
        }
    }

    int e0 = g_rowptr[node], e1 = g_rowptr[node + 1];
    for (int eb = e0; eb < e1; eb += 32) {
        int rem = e1 - eb;
        int2 ed = make_int2(0, 0);
        if (lane < rem) ed = g_edge[eb + lane];
        if (rem >= 32) {
            #pragma unroll 8
            for (int j = 0; j < 32; j++) {
                int   cj = __shfl_sync(0xffffffffu, ed.x, j);
                float wj = __int_as_float(__shfl_sync(0xffffffffu, ed.y, j));
                const __half* srow = supn + (size_t)cj * OUT + lane * V;
                if (V == 4) {
                    uint2 u = *(const uint2*)srow;
                    float2 f0 = __half22float2(*(const __half2*)&u.x);
                    float2 f1 = __half22float2(*(const __half2*)&u.y);
                    acc[0] = fmaf(wj, f0.x, acc[0]);
                    acc[1] = fmaf(wj, f0.y, acc[1]);
                    acc[2] = fmaf(wj, f1.x, acc[2]);
                    acc[3] = fmaf(wj, f1.y, acc[3]);
                } else {
                    uint32_t u = *(const uint32_t*)srow;
                    float2 f0 = __half22float2(*(const __half2*)&u);
                    acc[0] = fmaf(wj, f0.x, acc[0]);
                    acc[1] = fmaf(wj, f0.y, acc[1]);
                }
            }
        } else {
            for (int j = 0; j < rem; j++) {
                int   cj = __shfl_sync(0xffffffffu, ed.x, j);
                float wj = __int_as_float(__shfl_sync(0xffffffffu, ed.y, j));
                const __half* srow = supn + (size_t)cj * OUT + lane * V;
                if (V == 4) {
                    uint2 u = *(const uint2*)srow;
                    float2 f0 = __half22float2(*(const __half2*)&u.x);
                    float2 f1 = __half22float2(*(const __half2*)&u.y);
                    acc[0] = fmaf(wj, f0.x, acc[0]);
                    acc[1] = fmaf(wj, f0.y, acc[1]);
                    acc[2] = fmaf(wj, f1.x, acc[2]);
                    acc[3] = fmaf(wj, f1.y, acc[3]);
                } else {
                    uint32_t u = *(const uint32_t*)srow;
                    float2 f0 = __half22float2(*(const __half2*)&u);
                    acc[0] = fmaf(wj, f0.x, acc[0]);
                    acc[1] = fmaf(wj, f0.y, acc[1]);
                }
            }
        }
    }

    if (HOUT) {
        __half* orow = (__half*)out + (size_t)node * OUT + lane * V;
        __half2 a = __floats2half2_rn(fmaxf(acc[0], 0.f), fmaxf(acc[1], 0.f));
        __half2 b = __floats2half2_rn(fmaxf(acc[2], 0.f), fmaxf(acc[3], 0.f));
        *(uint2*)orow = make_uint2(*(unsigned*)&a, *(unsigned*)&b);
    } else {
        float* orow = (float*)out + (size_t)node * OUT + lane * V;
        #pragma unroll
        for (int i = 0; i < V; i++) orow[i] = fmaxf(acc[i], 0.f);
    }
}

// ======================= launch =======================
extern "C" void kernel_launch(void* const* d_in, const int* in_sizes, int n_in,
                              void* d_out, int out_size)
{
    const float* x    = (const float*)d_in[0];
    const int*   er   = (const int*)d_in[1];
    const int*   ec   = (const int*)d_in[2];
    const float* ev   = (const float*)d_in[3];
    const float* fc1w = (const float*)d_in[4];
    const float* fc1b = (const float*)d_in[5];
    const float* fc2w = (const float*)d_in[6];
    const float* fc2b = (const float*)d_in[7];
    const float* lng  = (const float*)d_in[8];
    const float* lnb  = (const float*)d_in[9];
    const float *wn[4], *wsf[4], *gb[4];
    for (int i = 0; i < 4; i++) {
        wn[i]  = (const float*)d_in[10 + 3 * i];
        wsf[i] = (const float*)d_in[11 + 3 * i];
        gb[i]  = (const float*)d_in[12 + 3 * i];
    }
    float* outp = (float*)d_out;

    __half *s0, *s1, *supn, *selfb, *wt;
    cudaGetSymbolAddress((void**)&s0,    g_h0);
    cudaGetSymbolAddress((void**)&s1,    g_h1);
    cudaGetSymbolAddress((void**)&supn,  g_supn);
    cudaGetSymbolAddress((void**)&selfb, g_self);
    cudaGetSymbolAddress((void**)&wt,    g_wt);
    auto WT = [&](int t) { return wt + (size_t)t * 16384; };

    cudaFuncSetAttribute(k_head, cudaFuncAttributeMaxDynamicSharedMemorySize, MM_SMEM);
    cudaFuncSetAttribute(k_mm,   cudaFuncAttributeMaxDynamicSharedMemorySize, MM_SMEM);

    const int MT = NPAD / TM;   // 1564

    k_wprep<<<dim3(128, 9), 128>>>(fc1w, fc2w, wn[0], wsf[0], wn[1], wsf[1],
                                   wn[2], wsf[2], wn[3], wsf[3], wt);            // 0
    k_zero_rowptr<<<(NP1 + 255) / 256, 256>>>();                                 // 1
    k_hist<<<(N_EDGES + 255) / 256, 256>>>(er);                                  // 2
    k_head<<<MT, 256, MM_SMEM>>>(x, WT(0), fc1b, fc2b, lng, lnb, s0);            // 3 <- profiled
    k_scan1<<<NSCAN_BLOCKS, 1024>>>();                                           // 4
    k_scan2<<<1, 1>>>();                                                         // 5
    k_scan3<<<NSCAN_BLOCKS, 1024>>>();                                           // 6
    k_fill<<<(N_EDGES + 255) / 256, 256>>>(er, ec, ev);                          // 7

    __half* cur = s0;
    __half* nxt = s1;
    for (int l = 0; l < 3; l++) {
        k_mm<<<MT, 256, MM_SMEM>>>(cur, WT(2 + 2 * l), supn, selfb, 1, 2);
        k_agg<128, 1><<<N_NODES / 8, 256>>>(supn, selfb, gb[l], nxt);
        __half* t = cur; cur = nxt; nxt = t;
    }

    k_mm<<<MT, 256, MM_SMEM>>>(cur, WT(8), supn, selfb, 3, 1);
    k_agg<64, 0><<<N_NODES / 8, 256>>>(supn, selfb, gb[3], outp);
}